// round 11
// baseline (speedup 1.0000x reference)
#include <cuda_runtime.h>
#include <cuda_fp16.h>
#include <cstdint>

// LabelwiseAttention: B=4, S=4096, D=256, C=8921
// scores = x @ W^T -> softmax over S -> logits = attn @ x
// Output: [logits (B*C*D) | attention (B*C*S)] fp32.
// GEMM1 (fp16 mma) writes p' = exp(score) as fp16 + per-slab rowsum partials.
// inv_kernel -> 1/l. scale kernel -> normalized fp32 attention.
// GEMM2 = pure fp16 GEMM on p' (2 CTAs/SM), logits scaled by 1/l in epilogue.

#define BDIM 4
#define SDIM 4096
#define DDIM 256
#define CDIM 8921
#define NSLAB (SDIM / 128)                 // 32 score slabs per row

// ---------------- scratch ---------------------------------------------------
__device__ __half g_xh[(size_t)BDIM * SDIM * DDIM];    // x  [b,s,d] fp16
__device__ __half g_xTh[(size_t)BDIM * DDIM * SDIM];   // xT [b,d,s] fp16
__device__ __half g_Wh[(size_t)CDIM * DDIM];           // W  [c,d]   fp16
__device__ __half g_ph[(size_t)BDIM * CDIM * SDIM];    // p' [b,c,s] fp16
__device__ float  g_lpart[(size_t)BDIM * CDIM * NSLAB];
__device__ float  g_linv[(size_t)BDIM * CDIM];

// ---------------- helpers ---------------------------------------------------
__device__ __forceinline__ uint32_t smem_u32(const void* p) {
    uint32_t a;
    asm("{ .reg .u64 t; cvta.to.shared.u64 t, %1; cvt.u32.u64 %0, t; }"
        : "=r"(a) : "l"(p));
    return a;
}

__device__ __forceinline__ void cp16(uint32_t dst, const void* src, int sz) {
    asm volatile("cp.async.cg.shared.global [%0], [%1], 16, %2;"
                 :: "r"(dst), "l"(src), "r"(sz) : "memory");
}
#define CP_COMMIT() asm volatile("cp.async.commit_group;" ::: "memory")
#define CP_WAIT1()  asm volatile("cp.async.wait_group 1;" ::: "memory")

__device__ __forceinline__ void ldm4(uint32_t* r, uint32_t addr) {
    asm volatile("ldmatrix.sync.aligned.m8n8.x4.shared.b16 {%0,%1,%2,%3}, [%4];"
                 : "=r"(r[0]), "=r"(r[1]), "=r"(r[2]), "=r"(r[3]) : "r"(addr));
}

__device__ __forceinline__ void mma_h(float* d, const uint32_t* a,
                                      uint32_t b0, uint32_t b1) {
    asm volatile(
        "mma.sync.aligned.m16n8k16.row.col.f32.f16.f16.f32 "
        "{%0,%1,%2,%3}, {%4,%5,%6,%7}, {%8,%9}, {%0,%1,%2,%3};"
        : "+f"(d[0]), "+f"(d[1]), "+f"(d[2]), "+f"(d[3])
        : "r"(a[0]), "r"(a[1]), "r"(a[2]), "r"(a[3]), "r"(b0), "r"(b1));
}

// ---------------- fp16 convert kernels --------------------------------------
__global__ void convert_W_kernel(const float* __restrict__ W) {
    int i = blockIdx.x * 256 + threadIdx.x;
    if (i < CDIM * DDIM) g_Wh[i] = __float2half(W[i]);
}

__global__ void convert_x_kernel(const float* __restrict__ x) {
    __shared__ __half t[32][33];
    const int b = blockIdx.z;
    const int s0 = blockIdx.x * 32, d0 = blockIdx.y * 32;
    const int tx = threadIdx.x, ty = threadIdx.y;  // 32x8
    const float* xb = x + (size_t)b * SDIM * DDIM;
#pragma unroll
    for (int i = 0; i < 32; i += 8) {
        const int s = s0 + ty + i;
        const __half h = __float2half(xb[(size_t)s * DDIM + d0 + tx]);
        g_xh[(size_t)b * SDIM * DDIM + (size_t)s * DDIM + d0 + tx] = h;
        t[ty + i][tx] = h;
    }
    __syncthreads();
#pragma unroll
    for (int i = 0; i < 32; i += 8) {
        const int d = d0 + ty + i;
        g_xTh[(size_t)b * DDIM * SDIM + (size_t)d * SDIM + s0 + tx] = t[tx][ty + i];
    }
}

// ---------------- GEMM1: p' = exp(Wh @ xh^T) fp16 + rowsum partials ---------
#define G1_PITCH 80
#define G1_TILE (128 * G1_PITCH)
#define G1_STAGE (2 * G1_TILE)
#define G1_TOTAL (2 * G1_STAGE)          // 40960

__global__ void __launch_bounds__(256, 1) gemm1_f16(
    const __half* __restrict__ A,        // [CDIM, K] W fp16
    const __half* __restrict__ B,        // [SDIM, K] x fp16, batch strided
    size_t sB,
    __half* __restrict__ Ph, size_t sP,  // p' out, fp16
    float* __restrict__ lpart, int K)
{
    extern __shared__ char sm[];
    const uint32_t sbase = smem_u32(sm);

    const int tid = threadIdx.x;
    const int lane = tid & 31;
    const int wid = tid >> 5;
    const int wm = wid & 1;
    const int wn = wid >> 1;
    const int b = blockIdx.z;
    const int m0 = blockIdx.y * 128;
    const int n0 = blockIdx.x * 128;
    const int Mv = CDIM;

    const __half* Bb = B + sB * b;

    float acc[4][4][4];
#pragma unroll
    for (int i = 0; i < 4; i++)
#pragma unroll
        for (int j = 0; j < 4; j++)
#pragma unroll
            for (int q = 0; q < 4; q++) acc[i][j][q] = 0.f;

    const int NC = K / 32;

    auto issue = [&](int kc) {
        const uint32_t st = sbase + (uint32_t)(kc & 1) * G1_STAGE;
        const int k0 = kc * 32;
#pragma unroll
        for (int it = 0; it < 2; it++) {
            const int idx = tid + it * 256;
            const int row = idx >> 2, ch = idx & 3;
            const uint32_t soff = (uint32_t)(row * G1_PITCH + ch * 16);
            const int ra = m0 + row;
            const int sz = (ra < Mv) ? 16 : 0;
            const int rac = (ra < Mv) ? ra : (Mv - 1);
            cp16(st + soff, A + (size_t)rac * K + k0 + ch * 8, sz);
            cp16(st + G1_TILE + soff, Bb + (size_t)(n0 + row) * K + k0 + ch * 8, 16);
        }
    };

    issue(0); CP_COMMIT();
    if (NC > 1) issue(1);
    CP_COMMIT();

    const uint32_t aoff = (uint32_t)((lane & 15) * G1_PITCH + (lane >> 4) * 16);
    const uint32_t boff = (uint32_t)(((lane & 7) + (lane >> 4) * 8) * G1_PITCH +
                                     ((lane >> 3) & 1) * 16);

    for (int kc = 0; kc < NC; kc++) {
        CP_WAIT1();
        __syncthreads();
        const uint32_t st = sbase + (uint32_t)(kc & 1) * G1_STAGE;

#pragma unroll
        for (int ks = 0; ks < 2; ks++) {
            const uint32_t kb = ks * 32;
            uint32_t af[4][4], bf[2][4];
#pragma unroll
            for (int mi = 0; mi < 4; mi++)
                ldm4(af[mi], st + (uint32_t)((wm * 64 + mi * 16) * G1_PITCH) + kb + aoff);
#pragma unroll
            for (int pi = 0; pi < 2; pi++)
                ldm4(bf[pi], st + G1_TILE +
                     (uint32_t)((wn * 32 + pi * 16) * G1_PITCH) + kb + boff);
#pragma unroll
            for (int mi = 0; mi < 4; mi++)
#pragma unroll
                for (int ni = 0; ni < 4; ni++) {
                    const int p = ni >> 1, w2 = (ni & 1) * 2;
                    mma_h(acc[mi][ni], af[mi], bf[p][w2], bf[p][w2 + 1]);
                }
        }
        __syncthreads();
        if (kc + 2 < NC) issue(kc + 2);
        CP_COMMIT();
    }

    // ---- epilogue: exp in registers -> fp16 p' + rowsum partials ----
#pragma unroll
    for (int mi = 0; mi < 4; mi++)
#pragma unroll
        for (int ni = 0; ni < 4; ni++)
#pragma unroll
            for (int q = 0; q < 4; q++)
                acc[mi][ni][q] = __expf(acc[mi][ni][q]);

    const int g = lane >> 2, cq = lane & 3;
    __half* pb = Ph + sP * b;
#pragma unroll
    for (int mi = 0; mi < 4; mi++) {
        const int r0 = m0 + wm * 64 + mi * 16 + g;
        const int r1 = r0 + 8;
#pragma unroll
        for (int ni = 0; ni < 4; ni++) {
            const int col = n0 + wn * 32 + ni * 8 + cq * 2;
            if (r0 < Mv)
                *(__half2*)(pb + (size_t)r0 * SDIM + col) =
                    __floats2half2_rn(acc[mi][ni][0], acc[mi][ni][1]);
            if (r1 < Mv)
                *(__half2*)(pb + (size_t)r1 * SDIM + col) =
                    __floats2half2_rn(acc[mi][ni][2], acc[mi][ni][3]);
        }
    }

    float ex[4][2];
#pragma unroll
    for (int mi = 0; mi < 4; mi++) {
        float s0 = 0.f, s1 = 0.f;
#pragma unroll
        for (int ni = 0; ni < 4; ni++) {
            s0 += acc[mi][ni][0] + acc[mi][ni][1];
            s1 += acc[mi][ni][2] + acc[mi][ni][3];
        }
        s0 += __shfl_xor_sync(0xffffffffu, s0, 1);
        s0 += __shfl_xor_sync(0xffffffffu, s0, 2);
        s1 += __shfl_xor_sync(0xffffffffu, s1, 1);
        s1 += __shfl_xor_sync(0xffffffffu, s1, 2);
        ex[mi][0] = s0; ex[mi][1] = s1;
    }
    __syncthreads();
    float* part = (float*)sm;               // [128][4]
    if (cq == 0) {
#pragma unroll
        for (int mi = 0; mi < 4; mi++) {
            part[(wm * 64 + mi * 16 + g) * 4 + wn] = ex[mi][0];
            part[(wm * 64 + mi * 16 + g + 8) * 4 + wn] = ex[mi][1];
        }
    }
    __syncthreads();
    if (tid < 128) {
        const int r = m0 + tid;
        if (r < Mv) {
            const float t = part[tid * 4] + part[tid * 4 + 1] +
                            part[tid * 4 + 2] + part[tid * 4 + 3];
            lpart[((size_t)b * CDIM + r) * NSLAB + blockIdx.x] = t;
        }
    }
}

// ---------------- inv: deterministic 32-slab reduce -> 1/l ------------------
__global__ void __launch_bounds__(256) inv_kernel(
    const float* __restrict__ lpart, float* __restrict__ linv)
{
    const int i = blockIdx.x * 256 + threadIdx.x;
    if (i < BDIM * CDIM) {
        const float* p = lpart + (size_t)i * NSLAB;
        float s = 0.f;
#pragma unroll
        for (int j = 0; j < NSLAB; j++) s += p[j];
        linv[i] = 1.0f / s;
    }
}

// ---------------- attn = float(p'h) * 1/l (streaming) -----------------------
__global__ void __launch_bounds__(256) attn_kernel(
    const __half* __restrict__ ph, const float* __restrict__ linv,
    float* __restrict__ attn)
{
    const float r = linv[blockIdx.x];
    const __half* p = ph + (size_t)blockIdx.x * SDIM;
    float* o = attn + (size_t)blockIdx.x * SDIM;
    const int tid = threadIdx.x;
#pragma unroll
    for (int i = 0; i < 2; i++) {
        const int e0 = (tid + i * 256) * 8;
        uint4 raw = *(const uint4*)(p + e0);
        const __half2* h2 = (const __half2*)&raw;
        float4 o0, o1;
        float2 a = __half22float2(h2[0]), bb = __half22float2(h2[1]);
        float2 c = __half22float2(h2[2]), d = __half22float2(h2[3]);
        o0.x = a.x * r;  o0.y = a.y * r;  o0.z = bb.x * r; o0.w = bb.y * r;
        o1.x = c.x * r;  o1.y = c.y * r;  o1.z = d.x * r;  o1.w = d.y * r;
        *(float4*)(o + e0) = o0;
        *(float4*)(o + e0 + 4) = o1;
    }
}

// ---------------- GEMM2: logits = (p'h @ xT^T) * 1/l ------------------------
// Same proven 256-thread 128x128 config; A batch-strided; epilogue scales.
__global__ void __launch_bounds__(256, 2) gemm2_f16(
    const __half* __restrict__ A,        // p' [CDIM, K] batch strided
    size_t sA,
    const __half* __restrict__ B,        // xT [DDIM, K] batch strided
    size_t sB,
    const float* __restrict__ linv,
    float* __restrict__ Out, size_t sO, int ldo, int K)
{
    extern __shared__ char sm[];
    const uint32_t sbase = smem_u32(sm);

    const int tid = threadIdx.x;
    const int lane = tid & 31;
    const int wid = tid >> 5;
    const int wm = wid & 1;
    const int wn = wid >> 1;
    const int b = blockIdx.z;
    const int m0 = blockIdx.y * 128;
    const int n0 = blockIdx.x * 128;
    const int Mv = CDIM;

    const __half* Ab = A + sA * b;
    const __half* Bb = B + sB * b;

    float acc[4][4][4];
#pragma unroll
    for (int i = 0; i < 4; i++)
#pragma unroll
        for (int j = 0; j < 4; j++)
#pragma unroll
            for (int q = 0; q < 4; q++) acc[i][j][q] = 0.f;

    const int NC = K / 32;

    auto issue = [&](int kc) {
        const uint32_t st = sbase + (uint32_t)(kc & 1) * G1_STAGE;
        const int k0 = kc * 32;
#pragma unroll
        for (int it = 0; it < 2; it++) {
            const int idx = tid + it * 256;
            const int row = idx >> 2, ch = idx & 3;
            const uint32_t soff = (uint32_t)(row * G1_PITCH + ch * 16);
            const int ra = m0 + row;
            const int sz = (ra < Mv) ? 16 : 0;
            const int rac = (ra < Mv) ? ra : (Mv - 1);
            cp16(st + soff, Ab + (size_t)rac * K + k0 + ch * 8, sz);
            cp16(st + G1_TILE + soff, Bb + (size_t)(n0 + row) * K + k0 + ch * 8, 16);
        }
    };

    issue(0); CP_COMMIT();
    if (NC > 1) issue(1);
    CP_COMMIT();

    const uint32_t aoff = (uint32_t)((lane & 15) * G1_PITCH + (lane >> 4) * 16);
    const uint32_t boff = (uint32_t)(((lane & 7) + (lane >> 4) * 8) * G1_PITCH +
                                     ((lane >> 3) & 1) * 16);

    for (int kc = 0; kc < NC; kc++) {
        CP_WAIT1();
        __syncthreads();
        const uint32_t st = sbase + (uint32_t)(kc & 1) * G1_STAGE;

#pragma unroll
        for (int ks = 0; ks < 2; ks++) {
            const uint32_t kb = ks * 32;
            uint32_t af[4][4], bf[2][4];
#pragma unroll
            for (int mi = 0; mi < 4; mi++)
                ldm4(af[mi], st + (uint32_t)((wm * 64 + mi * 16) * G1_PITCH) + kb + aoff);
#pragma unroll
            for (int pi = 0; pi < 2; pi++)
                ldm4(bf[pi], st + G1_TILE +
                     (uint32_t)((wn * 32 + pi * 16) * G1_PITCH) + kb + boff);
#pragma unroll
            for (int mi = 0; mi < 4; mi++)
#pragma unroll
                for (int ni = 0; ni < 4; ni++) {
                    const int p = ni >> 1, w2 = (ni & 1) * 2;
                    mma_h(acc[mi][ni], af[mi], bf[p][w2], bf[p][w2 + 1]);
                }
        }
        __syncthreads();
        if (kc + 2 < NC) issue(kc + 2);
        CP_COMMIT();
    }

    const int g = lane >> 2, cq = lane & 3;
    float* ob = Out + sO * b;
#pragma unroll
    for (int mi = 0; mi < 4; mi++) {
        const int r0 = m0 + wm * 64 + mi * 16 + g;
        const int r1 = r0 + 8;
        const float i0 = (r0 < Mv) ? linv[(size_t)b * CDIM + r0] : 0.f;
        const float i1 = (r1 < Mv) ? linv[(size_t)b * CDIM + r1] : 0.f;
#pragma unroll
        for (int ni = 0; ni < 4; ni++) {
            const int col = n0 + wn * 32 + ni * 8 + cq * 2;
            if (r0 < Mv)
                *(float2*)(ob + (size_t)r0 * ldo + col) =
                    make_float2(acc[mi][ni][0] * i0, acc[mi][ni][1] * i0);
            if (r1 < Mv)
                *(float2*)(ob + (size_t)r1 * ldo + col) =
                    make_float2(acc[mi][ni][2] * i1, acc[mi][ni][3] * i1);
        }
    }
}

// ---------------------------------------------------------------------------
extern "C" void kernel_launch(void* const* d_in, const int* in_sizes, int n_in,
                              void* d_out, int out_size)
{
    const float* x = (const float*)d_in[0];  // [B, S, D]
    const float* W = (const float*)d_in[1];  // [C, D]

    float* logits = (float*)d_out;                               // [B, C, D]
    float* attn   = (float*)d_out + (size_t)BDIM * CDIM * DDIM;  // [B, C, S]

    cudaFuncSetAttribute(gemm1_f16,
                         cudaFuncAttributeMaxDynamicSharedMemorySize, G1_TOTAL);
    cudaFuncSetAttribute(gemm2_f16,
                         cudaFuncAttributeMaxDynamicSharedMemorySize, G1_TOTAL);

    void *p_xh, *p_xTh, *p_Wh, *p_ph, *p_lpart, *p_linv;
    cudaGetSymbolAddress(&p_xh, g_xh);
    cudaGetSymbolAddress(&p_xTh, g_xTh);
    cudaGetSymbolAddress(&p_Wh, g_Wh);
    cudaGetSymbolAddress(&p_ph, g_ph);
    cudaGetSymbolAddress(&p_lpart, g_lpart);
    cudaGetSymbolAddress(&p_linv, g_linv);

    // 1) fp16 conversions of W and x (+ transposed x)
    convert_W_kernel<<<(CDIM * DDIM + 255) / 256, 256>>>(W);
    convert_x_kernel<<<dim3(SDIM / 32, DDIM / 32, BDIM), dim3(32, 8)>>>(x);

    // 2) p' = exp(scores) fp16 + rowsum partials
    gemm1_f16<<<dim3(SDIM / 128, (CDIM + 127) / 128, BDIM), 256, G1_TOTAL>>>(
        (const __half*)p_Wh, (const __half*)p_xh, (size_t)SDIM * DDIM,
        (__half*)p_ph, (size_t)CDIM * SDIM, (float*)p_lpart, DDIM);

    // 3) 1/l per row
    inv_kernel<<<(BDIM * CDIM + 255) / 256, 256>>>(
        (const float*)p_lpart, (float*)p_linv);

    // 4) normalized fp32 attention (streaming)
    attn_kernel<<<BDIM * CDIM, 256>>>(
        (const __half*)p_ph, (const float*)p_linv, attn);

    // 5) logits = (p' @ xT^T) * 1/l  — pure fp16 GEMM, 2 CTAs/SM
    gemm2_f16<<<dim3(DDIM / 128, (CDIM + 127) / 128, BDIM), 256, G1_TOTAL>>>(
        (const __half*)p_ph, (size_t)CDIM * SDIM,
        (const __half*)p_xTh, (size_t)DDIM * SDIM,
        (const float*)p_linv,
        logits, (size_t)CDIM * DDIM, DDIM, SDIM);
}

// round 12
// speedup vs baseline: 1.0174x; 1.0174x over previous
#include <cuda_runtime.h>
#include <cuda_fp16.h>
#include <cstdint>

// LabelwiseAttention: B=4, S=4096, D=256, C=8921
// scores = x @ W^T -> softmax over S -> logits = attn @ x
// Output: [logits (B*C*D) | attention (B*C*S)] fp32.
// GEMM1 (fp16 mma) -> p' = exp(score) fp16 + per-slab rowsum partials.
// inv_kernel -> 1/l.
// Fused GEMM2: stages p' tiles (already fp16 = MMA A operand directly, no
// convert phase), MMA vs xT, and writes attn = p'*1/l from the same staged
// bytes; logits scaled by 1/l in epilogue.

#define BDIM 4
#define SDIM 4096
#define DDIM 256
#define CDIM 8921
#define NSLAB (SDIM / 128)                 // 32 score slabs per row

// ---------------- scratch ---------------------------------------------------
__device__ __half g_xh[(size_t)BDIM * SDIM * DDIM];    // x  [b,s,d] fp16
__device__ __half g_xTh[(size_t)BDIM * DDIM * SDIM];   // xT [b,d,s] fp16
__device__ __half g_Wh[(size_t)CDIM * DDIM];           // W  [c,d]   fp16
__device__ __half g_ph[(size_t)BDIM * CDIM * SDIM];    // p' [b,c,s] fp16
__device__ float  g_lpart[(size_t)BDIM * CDIM * NSLAB];
__device__ float  g_linv[(size_t)BDIM * CDIM];

// ---------------- helpers ---------------------------------------------------
__device__ __forceinline__ uint32_t smem_u32(const void* p) {
    uint32_t a;
    asm("{ .reg .u64 t; cvta.to.shared.u64 t, %1; cvt.u32.u64 %0, t; }"
        : "=r"(a) : "l"(p));
    return a;
}

__device__ __forceinline__ void cp16(uint32_t dst, const void* src, int sz) {
    asm volatile("cp.async.cg.shared.global [%0], [%1], 16, %2;"
                 :: "r"(dst), "l"(src), "r"(sz) : "memory");
}
#define CP_COMMIT() asm volatile("cp.async.commit_group;" ::: "memory")
#define CP_WAIT1()  asm volatile("cp.async.wait_group 1;" ::: "memory")

__device__ __forceinline__ void ldm4(uint32_t* r, uint32_t addr) {
    asm volatile("ldmatrix.sync.aligned.m8n8.x4.shared.b16 {%0,%1,%2,%3}, [%4];"
                 : "=r"(r[0]), "=r"(r[1]), "=r"(r[2]), "=r"(r[3]) : "r"(addr));
}

__device__ __forceinline__ void mma_h(float* d, const uint32_t* a,
                                      uint32_t b0, uint32_t b1) {
    asm volatile(
        "mma.sync.aligned.m16n8k16.row.col.f32.f16.f16.f32 "
        "{%0,%1,%2,%3}, {%4,%5,%6,%7}, {%8,%9}, {%0,%1,%2,%3};"
        : "+f"(d[0]), "+f"(d[1]), "+f"(d[2]), "+f"(d[3])
        : "r"(a[0]), "r"(a[1]), "r"(a[2]), "r"(a[3]), "r"(b0), "r"(b1));
}

// ---------------- fp16 convert kernels --------------------------------------
__global__ void convert_W_kernel(const float* __restrict__ W) {
    int i = blockIdx.x * 256 + threadIdx.x;
    if (i < CDIM * DDIM) g_Wh[i] = __float2half(W[i]);
}

__global__ void convert_x_kernel(const float* __restrict__ x) {
    __shared__ __half t[32][33];
    const int b = blockIdx.z;
    const int s0 = blockIdx.x * 32, d0 = blockIdx.y * 32;
    const int tx = threadIdx.x, ty = threadIdx.y;  // 32x8
    const float* xb = x + (size_t)b * SDIM * DDIM;
#pragma unroll
    for (int i = 0; i < 32; i += 8) {
        const int s = s0 + ty + i;
        const __half h = __float2half(xb[(size_t)s * DDIM + d0 + tx]);
        g_xh[(size_t)b * SDIM * DDIM + (size_t)s * DDIM + d0 + tx] = h;
        t[ty + i][tx] = h;
    }
    __syncthreads();
#pragma unroll
    for (int i = 0; i < 32; i += 8) {
        const int d = d0 + ty + i;
        g_xTh[(size_t)b * DDIM * SDIM + (size_t)d * SDIM + s0 + tx] = t[tx][ty + i];
    }
}

// ---------------- GEMM1: p' = exp(Wh @ xh^T) fp16 + rowsum partials ---------
#define G1_PITCH 80
#define G1_TILE (128 * G1_PITCH)
#define G1_STAGE (2 * G1_TILE)
#define G1_TOTAL (2 * G1_STAGE)          // 40960

__global__ void __launch_bounds__(256, 1) gemm1_f16(
    const __half* __restrict__ A,        // [CDIM, K] W fp16
    const __half* __restrict__ B,        // [SDIM, K] x fp16, batch strided
    size_t sB,
    __half* __restrict__ Ph, size_t sP,  // p' out, fp16
    float* __restrict__ lpart, int K)
{
    extern __shared__ char sm[];
    const uint32_t sbase = smem_u32(sm);

    const int tid = threadIdx.x;
    const int lane = tid & 31;
    const int wid = tid >> 5;
    const int wm = wid & 1;
    const int wn = wid >> 1;
    const int b = blockIdx.z;
    const int m0 = blockIdx.y * 128;
    const int n0 = blockIdx.x * 128;
    const int Mv = CDIM;

    const __half* Bb = B + sB * b;

    float acc[4][4][4];
#pragma unroll
    for (int i = 0; i < 4; i++)
#pragma unroll
        for (int j = 0; j < 4; j++)
#pragma unroll
            for (int q = 0; q < 4; q++) acc[i][j][q] = 0.f;

    const int NC = K / 32;

    auto issue = [&](int kc) {
        const uint32_t st = sbase + (uint32_t)(kc & 1) * G1_STAGE;
        const int k0 = kc * 32;
#pragma unroll
        for (int it = 0; it < 2; it++) {
            const int idx = tid + it * 256;
            const int row = idx >> 2, ch = idx & 3;
            const uint32_t soff = (uint32_t)(row * G1_PITCH + ch * 16);
            const int ra = m0 + row;
            const int sz = (ra < Mv) ? 16 : 0;
            const int rac = (ra < Mv) ? ra : (Mv - 1);
            cp16(st + soff, A + (size_t)rac * K + k0 + ch * 8, sz);
            cp16(st + G1_TILE + soff, Bb + (size_t)(n0 + row) * K + k0 + ch * 8, 16);
        }
    };

    issue(0); CP_COMMIT();
    if (NC > 1) issue(1);
    CP_COMMIT();

    const uint32_t aoff = (uint32_t)((lane & 15) * G1_PITCH + (lane >> 4) * 16);
    const uint32_t boff = (uint32_t)(((lane & 7) + (lane >> 4) * 8) * G1_PITCH +
                                     ((lane >> 3) & 1) * 16);

    for (int kc = 0; kc < NC; kc++) {
        CP_WAIT1();
        __syncthreads();
        const uint32_t st = sbase + (uint32_t)(kc & 1) * G1_STAGE;

#pragma unroll
        for (int ks = 0; ks < 2; ks++) {
            const uint32_t kb = ks * 32;
            uint32_t af[4][4], bf[2][4];
#pragma unroll
            for (int mi = 0; mi < 4; mi++)
                ldm4(af[mi], st + (uint32_t)((wm * 64 + mi * 16) * G1_PITCH) + kb + aoff);
#pragma unroll
            for (int pi = 0; pi < 2; pi++)
                ldm4(bf[pi], st + G1_TILE +
                     (uint32_t)((wn * 32 + pi * 16) * G1_PITCH) + kb + boff);
#pragma unroll
            for (int mi = 0; mi < 4; mi++)
#pragma unroll
                for (int ni = 0; ni < 4; ni++) {
                    const int p = ni >> 1, w2 = (ni & 1) * 2;
                    mma_h(acc[mi][ni], af[mi], bf[p][w2], bf[p][w2 + 1]);
                }
        }
        __syncthreads();
        if (kc + 2 < NC) issue(kc + 2);
        CP_COMMIT();
    }

    // ---- epilogue: exp in registers -> fp16 p' + rowsum partials ----
#pragma unroll
    for (int mi = 0; mi < 4; mi++)
#pragma unroll
        for (int ni = 0; ni < 4; ni++)
#pragma unroll
            for (int q = 0; q < 4; q++)
                acc[mi][ni][q] = __expf(acc[mi][ni][q]);

    const int g = lane >> 2, cq = lane & 3;
    __half* pb = Ph + sP * b;
#pragma unroll
    for (int mi = 0; mi < 4; mi++) {
        const int r0 = m0 + wm * 64 + mi * 16 + g;
        const int r1 = r0 + 8;
#pragma unroll
        for (int ni = 0; ni < 4; ni++) {
            const int col = n0 + wn * 32 + ni * 8 + cq * 2;
            if (r0 < Mv)
                *(__half2*)(pb + (size_t)r0 * SDIM + col) =
                    __floats2half2_rn(acc[mi][ni][0], acc[mi][ni][1]);
            if (r1 < Mv)
                *(__half2*)(pb + (size_t)r1 * SDIM + col) =
                    __floats2half2_rn(acc[mi][ni][2], acc[mi][ni][3]);
        }
    }

    float ex[4][2];
#pragma unroll
    for (int mi = 0; mi < 4; mi++) {
        float s0 = 0.f, s1 = 0.f;
#pragma unroll
        for (int ni = 0; ni < 4; ni++) {
            s0 += acc[mi][ni][0] + acc[mi][ni][1];
            s1 += acc[mi][ni][2] + acc[mi][ni][3];
        }
        s0 += __shfl_xor_sync(0xffffffffu, s0, 1);
        s0 += __shfl_xor_sync(0xffffffffu, s0, 2);
        s1 += __shfl_xor_sync(0xffffffffu, s1, 1);
        s1 += __shfl_xor_sync(0xffffffffu, s1, 2);
        ex[mi][0] = s0; ex[mi][1] = s1;
    }
    __syncthreads();
    float* part = (float*)sm;               // [128][4]
    if (cq == 0) {
#pragma unroll
        for (int mi = 0; mi < 4; mi++) {
            part[(wm * 64 + mi * 16 + g) * 4 + wn] = ex[mi][0];
            part[(wm * 64 + mi * 16 + g + 8) * 4 + wn] = ex[mi][1];
        }
    }
    __syncthreads();
    if (tid < 128) {
        const int r = m0 + tid;
        if (r < Mv) {
            const float t = part[tid * 4] + part[tid * 4 + 1] +
                            part[tid * 4 + 2] + part[tid * 4 + 3];
            lpart[((size_t)b * CDIM + r) * NSLAB + blockIdx.x] = t;
        }
    }
}

// ---------------- inv: deterministic 32-slab reduce -> 1/l ------------------
__global__ void __launch_bounds__(256) inv_kernel(
    const float* __restrict__ lpart, float* __restrict__ linv)
{
    const int i = blockIdx.x * 256 + threadIdx.x;
    if (i < BDIM * CDIM) {
        const float* p = lpart + (size_t)i * NSLAB;
        float s = 0.f;
#pragma unroll
        for (int j = 0; j < NSLAB; j++) s += p[j];
        linv[i] = 1.0f / s;
    }
}

// ================= Fused GEMM2 + attn write =================================
// 128 c-rows x 256 D cols per block; K over S in 32-chunks, 3-stage ring.
// Staged p' (fp16) is the MMA A operand directly; attn-write phase reads the
// same staged bytes (own cp.async data) and stores p'*1/l as fp32.
#define FKC 32
#define FA_B (128 * G1_PITCH)               // 10240
#define FB_B (256 * G1_PITCH)               // 20480
#define F_A   512
#define F_B   (F_A + 3 * FA_B)              // 31232
#define F_TOTAL (F_B + 3 * FB_B)            // 92672

__global__ void __launch_bounds__(512, 1) fused_gemm2(
    const __half* __restrict__ Ph,          // p' [B,C,S] fp16
    const __half* __restrict__ xTh,
    const float* __restrict__ linv,
    float* __restrict__ attn,               // [B,C,S] fp32 out
    float* __restrict__ logits)             // [B,C,D] fp32 out
{
    extern __shared__ char sm[];
    const uint32_t sbase = smem_u32(sm);
    float* sl = (float*)sm;                 // 128 x 1/l

    const int tid = threadIdx.x;
    const int lane = tid & 31;
    const int wid = tid >> 5;
    const int wn = wid & 3;                 // 4 n-slabs of 64
    const int wm = wid >> 2;                // 4 m-slabs of 32
    const int b = blockIdx.y;
    const int c0 = blockIdx.x * 128;
    const int Mv = CDIM;

    const __half* pb = Ph + (size_t)b * CDIM * SDIM;
    const __half* Bh = xTh + (size_t)b * DDIM * SDIM;
    float* ab = attn + (size_t)b * CDIM * SDIM;

    float acc[2][8][4];
#pragma unroll
    for (int i = 0; i < 2; i++)
#pragma unroll
        for (int j = 0; j < 8; j++)
#pragma unroll
            for (int q = 0; q < 4; q++) acc[i][j][q] = 0.f;

    if (tid < 128) {
        const int r = c0 + tid;
        sl[tid] = (r < Mv) ? linv[(size_t)b * CDIM + r] : 0.f;
    }

    // A-stage mapping: thread tid owns (row = tid>>2, ch = tid&3) — the SAME
    // 16B it later reads in the attn-write phase (no cross-thread dependency).
    const int arow = tid >> 2, ach = tid & 3;
    const int ar = c0 + arow;
    const int asz = (ar < Mv) ? 16 : 0;
    const __half* asrc = pb + (size_t)((ar < Mv) ? ar : (Mv - 1)) * SDIM + ach * 8;

    auto issue = [&](int kc) {
        const int k0 = kc * FKC;
        const int s3 = kc % 3;
        cp16(sbase + F_A + (uint32_t)s3 * FA_B +
             (uint32_t)(arow * G1_PITCH + ach * 16), asrc + k0, asz);
        const uint32_t stB = sbase + F_B + (uint32_t)s3 * FB_B;
#pragma unroll
        for (int it = 0; it < 2; it++) {
            const int idx = tid + it * 512;
            const int row = idx >> 2, ch = idx & 3;
            cp16(stB + (uint32_t)(row * G1_PITCH + ch * 16),
                 Bh + (size_t)row * SDIM + k0 + ch * 8, 16);
        }
    };

    issue(0); CP_COMMIT();
    issue(1); CP_COMMIT();
    issue(2); CP_COMMIT();
    __syncthreads();            // sl visible

    const uint32_t aoff = (uint32_t)((lane & 15) * G1_PITCH + (lane >> 4) * 16);
    const uint32_t boff = (uint32_t)(((lane & 7) + (lane >> 4) * 8) * G1_PITCH +
                                     ((lane >> 3) & 1) * 16);

    const int NC = SDIM / FKC;              // 128
    for (int kc = 0; kc < NC; kc++) {
        const int k0 = kc * FKC;
        const int s3 = kc % 3;
        CP_WAIT1();             // stage kc complete (3 groups in flight max)
        __syncthreads();        // cross-thread visibility for ldmatrix

        // ---- attn write (fire-and-forget; reads own staged bytes) ----
        if (ar < Mv) {
            const float iv = sl[arow];
            uint4 raw = *(const uint4*)(sm + F_A + s3 * FA_B +
                                        arow * G1_PITCH + ach * 16);
            const __half2* h2 = (const __half2*)&raw;
            float2 a0 = __half22float2(h2[0]), a1 = __half22float2(h2[1]);
            float2 a2 = __half22float2(h2[2]), a3 = __half22float2(h2[3]);
            float4 o0 = make_float4(a0.x * iv, a0.y * iv, a1.x * iv, a1.y * iv);
            float4 o1 = make_float4(a2.x * iv, a2.y * iv, a3.x * iv, a3.y * iv);
            float* op = ab + (size_t)ar * SDIM + k0 + ach * 8;
            *(float4*)op = o0;
            *(float4*)(op + 4) = o1;
        }

        // ---- MMA: A = staged p' (fp16), B = staged xT ----
        const uint32_t stA = sbase + F_A + (uint32_t)s3 * FA_B;
        const uint32_t stB = sbase + F_B + (uint32_t)s3 * FB_B;
#pragma unroll
        for (int ks = 0; ks < 2; ks++) {
            const uint32_t kb = ks * 32;
            uint32_t af[2][4];
#pragma unroll
            for (int mi = 0; mi < 2; mi++)
                ldm4(af[mi], stA + (uint32_t)((wm * 32 + mi * 16) * G1_PITCH) + kb + aoff);
#pragma unroll
            for (int pi = 0; pi < 4; pi++) {
                uint32_t bf[4];
                ldm4(bf, stB + (uint32_t)((wn * 64 + pi * 16) * G1_PITCH) + kb + boff);
#pragma unroll
                for (int mi = 0; mi < 2; mi++)
#pragma unroll
                    for (int q = 0; q < 2; q++)
                        mma_h(acc[mi][pi * 2 + q], af[mi], bf[q * 2], bf[q * 2 + 1]);
            }
        }
        __syncthreads();        // stage kc reads complete before overwrite
        if (kc + 3 < NC) issue(kc + 3);
        CP_COMMIT();
    }

    // ---- epilogue: normalized logits ----
    float* ob = logits + (size_t)b * CDIM * DDIM;
    const int g = lane >> 2, cq = lane & 3;
#pragma unroll
    for (int mi = 0; mi < 2; mi++) {
        const int lr0 = wm * 32 + mi * 16 + g;
        const int lr1 = lr0 + 8;
        const float i0 = sl[lr0], i1 = sl[lr1];
        const int r0 = c0 + lr0, r1 = c0 + lr1;
#pragma unroll
        for (int ni = 0; ni < 8; ni++) {
            const int col = wn * 64 + ni * 8 + cq * 2;
            if (r0 < Mv)
                *(float2*)(ob + (size_t)r0 * DDIM + col) =
                    make_float2(acc[mi][ni][0] * i0, acc[mi][ni][1] * i0);
            if (r1 < Mv)
                *(float2*)(ob + (size_t)r1 * DDIM + col) =
                    make_float2(acc[mi][ni][2] * i1, acc[mi][ni][3] * i1);
        }
    }
}

// ---------------------------------------------------------------------------
extern "C" void kernel_launch(void* const* d_in, const int* in_sizes, int n_in,
                              void* d_out, int out_size)
{
    const float* x = (const float*)d_in[0];  // [B, S, D]
    const float* W = (const float*)d_in[1];  // [C, D]

    float* logits = (float*)d_out;                               // [B, C, D]
    float* attn   = (float*)d_out + (size_t)BDIM * CDIM * DDIM;  // [B, C, S]

    cudaFuncSetAttribute(gemm1_f16,
                         cudaFuncAttributeMaxDynamicSharedMemorySize, G1_TOTAL);
    cudaFuncSetAttribute(fused_gemm2,
                         cudaFuncAttributeMaxDynamicSharedMemorySize, F_TOTAL);

    void *p_xh, *p_xTh, *p_Wh, *p_ph, *p_lpart, *p_linv;
    cudaGetSymbolAddress(&p_xh, g_xh);
    cudaGetSymbolAddress(&p_xTh, g_xTh);
    cudaGetSymbolAddress(&p_Wh, g_Wh);
    cudaGetSymbolAddress(&p_ph, g_ph);
    cudaGetSymbolAddress(&p_lpart, g_lpart);
    cudaGetSymbolAddress(&p_linv, g_linv);

    // 1) fp16 conversions of W and x (+ transposed x)
    convert_W_kernel<<<(CDIM * DDIM + 255) / 256, 256>>>(W);
    convert_x_kernel<<<dim3(SDIM / 32, DDIM / 32, BDIM), dim3(32, 8)>>>(x);

    // 2) p' = exp(scores) fp16 + rowsum partials
    gemm1_f16<<<dim3(SDIM / 128, (CDIM + 127) / 128, BDIM), 256, G1_TOTAL>>>(
        (const __half*)p_Wh, (const __half*)p_xh, (size_t)SDIM * DDIM,
        (__half*)p_ph, (size_t)CDIM * SDIM, (float*)p_lpart, DDIM);

    // 3) 1/l per row
    inv_kernel<<<(BDIM * CDIM + 255) / 256, 256>>>(
        (const float*)p_lpart, (float*)p_linv);

    // 4) fused: logits = (p' @ xT^T)*1/l  and  attn = p'*1/l
    fused_gemm2<<<dim3((CDIM + 127) / 128, BDIM), 512, F_TOTAL>>>(
        (const __half*)p_ph, (const __half*)p_xTh, (const float*)p_linv,
        attn, logits);
}

// round 13
// speedup vs baseline: 1.1333x; 1.1140x over previous
#include <cuda_runtime.h>
#include <cuda_fp16.h>
#include <cstdint>

// LabelwiseAttention: B=4, S=4096, D=256, C=8921
// scores = x @ W^T -> softmax over S -> logits = attn @ x
// Output: [logits (B*C*D) | attention (B*C*S)] fp32.
// GEMM1 (fp16 mma, 2 CTAs/SM) -> p' = exp(score) fp16 + rowsum partials.
// inv_kernel -> 1/l.
// GEMM2 fused (256 thr, D split x2, 2 CTAs/SM): stages p' (fp16 = MMA A
// operand directly), MMA vs xT, n-tile 0 also writes attn = p'*1/l from its
// own staged bytes; logits scaled by 1/l in epilogue.

#define BDIM 4
#define SDIM 4096
#define DDIM 256
#define CDIM 8921
#define NSLAB (SDIM / 128)                 // 32 score slabs per row

// ---------------- scratch ---------------------------------------------------
__device__ __half g_xh[(size_t)BDIM * SDIM * DDIM];    // x  [b,s,d] fp16
__device__ __half g_xTh[(size_t)BDIM * DDIM * SDIM];   // xT [b,d,s] fp16
__device__ __half g_Wh[(size_t)CDIM * DDIM];           // W  [c,d]   fp16
__device__ __half g_ph[(size_t)BDIM * CDIM * SDIM];    // p' [b,c,s] fp16
__device__ float  g_lpart[(size_t)BDIM * CDIM * NSLAB];
__device__ float  g_linv[(size_t)BDIM * CDIM];

// ---------------- helpers ---------------------------------------------------
__device__ __forceinline__ uint32_t smem_u32(const void* p) {
    uint32_t a;
    asm("{ .reg .u64 t; cvta.to.shared.u64 t, %1; cvt.u32.u64 %0, t; }"
        : "=r"(a) : "l"(p));
    return a;
}

__device__ __forceinline__ void cp16(uint32_t dst, const void* src, int sz) {
    asm volatile("cp.async.cg.shared.global [%0], [%1], 16, %2;"
                 :: "r"(dst), "l"(src), "r"(sz) : "memory");
}
#define CP_COMMIT() asm volatile("cp.async.commit_group;" ::: "memory")
#define CP_WAIT1()  asm volatile("cp.async.wait_group 1;" ::: "memory")
#define CP_WAIT2()  asm volatile("cp.async.wait_group 2;" ::: "memory")

__device__ __forceinline__ void ldm4(uint32_t* r, uint32_t addr) {
    asm volatile("ldmatrix.sync.aligned.m8n8.x4.shared.b16 {%0,%1,%2,%3}, [%4];"
                 : "=r"(r[0]), "=r"(r[1]), "=r"(r[2]), "=r"(r[3]) : "r"(addr));
}

__device__ __forceinline__ void mma_h(float* d, const uint32_t* a,
                                      uint32_t b0, uint32_t b1) {
    asm volatile(
        "mma.sync.aligned.m16n8k16.row.col.f32.f16.f16.f32 "
        "{%0,%1,%2,%3}, {%4,%5,%6,%7}, {%8,%9}, {%0,%1,%2,%3};"
        : "+f"(d[0]), "+f"(d[1]), "+f"(d[2]), "+f"(d[3])
        : "r"(a[0]), "r"(a[1]), "r"(a[2]), "r"(a[3]), "r"(b0), "r"(b1));
}

// ---------------- fp16 convert kernels --------------------------------------
__global__ void convert_W_kernel(const float* __restrict__ W) {
    int i = blockIdx.x * 256 + threadIdx.x;
    if (i < CDIM * DDIM) g_Wh[i] = __float2half(W[i]);
}

__global__ void convert_x_kernel(const float* __restrict__ x) {
    __shared__ __half t[32][33];
    const int b = blockIdx.z;
    const int s0 = blockIdx.x * 32, d0 = blockIdx.y * 32;
    const int tx = threadIdx.x, ty = threadIdx.y;  // 32x8
    const float* xb = x + (size_t)b * SDIM * DDIM;
#pragma unroll
    for (int i = 0; i < 32; i += 8) {
        const int s = s0 + ty + i;
        const __half h = __float2half(xb[(size_t)s * DDIM + d0 + tx]);
        g_xh[(size_t)b * SDIM * DDIM + (size_t)s * DDIM + d0 + tx] = h;
        t[ty + i][tx] = h;
    }
    __syncthreads();
#pragma unroll
    for (int i = 0; i < 32; i += 8) {
        const int d = d0 + ty + i;
        g_xTh[(size_t)b * DDIM * SDIM + (size_t)d * SDIM + s0 + tx] = t[tx][ty + i];
    }
}

// ---------------- GEMM1: p' = exp(Wh @ xh^T) fp16 + rowsum partials ---------
#define G1_PITCH 80
#define G1_TILE (128 * G1_PITCH)
#define G1_STAGE (2 * G1_TILE)
#define G1_TOTAL (2 * G1_STAGE)          // 40960

__global__ void __launch_bounds__(256, 2) gemm1_f16(
    const __half* __restrict__ A,        // [CDIM, K] W fp16
    const __half* __restrict__ B,        // [SDIM, K] x fp16, batch strided
    size_t sB,
    __half* __restrict__ Ph, size_t sP,  // p' out, fp16
    float* __restrict__ lpart, int K)
{
    extern __shared__ char sm[];
    const uint32_t sbase = smem_u32(sm);

    const int tid = threadIdx.x;
    const int lane = tid & 31;
    const int wid = tid >> 5;
    const int wm = wid & 1;
    const int wn = wid >> 1;
    const int b = blockIdx.z;
    const int m0 = blockIdx.y * 128;
    const int n0 = blockIdx.x * 128;
    const int Mv = CDIM;

    const __half* Bb = B + sB * b;

    float acc[4][4][4];
#pragma unroll
    for (int i = 0; i < 4; i++)
#pragma unroll
        for (int j = 0; j < 4; j++)
#pragma unroll
            for (int q = 0; q < 4; q++) acc[i][j][q] = 0.f;

    const int NC = K / 32;

    auto issue = [&](int kc) {
        const uint32_t st = sbase + (uint32_t)(kc & 1) * G1_STAGE;
        const int k0 = kc * 32;
#pragma unroll
        for (int it = 0; it < 2; it++) {
            const int idx = tid + it * 256;
            const int row = idx >> 2, ch = idx & 3;
            const uint32_t soff = (uint32_t)(row * G1_PITCH + ch * 16);
            const int ra = m0 + row;
            const int sz = (ra < Mv) ? 16 : 0;
            const int rac = (ra < Mv) ? ra : (Mv - 1);
            cp16(st + soff, A + (size_t)rac * K + k0 + ch * 8, sz);
            cp16(st + G1_TILE + soff, Bb + (size_t)(n0 + row) * K + k0 + ch * 8, 16);
        }
    };

    issue(0); CP_COMMIT();
    if (NC > 1) issue(1);
    CP_COMMIT();

    const uint32_t aoff = (uint32_t)((lane & 15) * G1_PITCH + (lane >> 4) * 16);
    const uint32_t boff = (uint32_t)(((lane & 7) + (lane >> 4) * 8) * G1_PITCH +
                                     ((lane >> 3) & 1) * 16);

    for (int kc = 0; kc < NC; kc++) {
        CP_WAIT1();
        __syncthreads();
        const uint32_t st = sbase + (uint32_t)(kc & 1) * G1_STAGE;

#pragma unroll
        for (int ks = 0; ks < 2; ks++) {
            const uint32_t kb = ks * 32;
            uint32_t af[4][4], bf[2][4];
#pragma unroll
            for (int mi = 0; mi < 4; mi++)
                ldm4(af[mi], st + (uint32_t)((wm * 64 + mi * 16) * G1_PITCH) + kb + aoff);
#pragma unroll
            for (int pi = 0; pi < 2; pi++)
                ldm4(bf[pi], st + G1_TILE +
                     (uint32_t)((wn * 32 + pi * 16) * G1_PITCH) + kb + boff);
#pragma unroll
            for (int mi = 0; mi < 4; mi++)
#pragma unroll
                for (int ni = 0; ni < 4; ni++) {
                    const int p = ni >> 1, w2 = (ni & 1) * 2;
                    mma_h(acc[mi][ni], af[mi], bf[p][w2], bf[p][w2 + 1]);
                }
        }
        __syncthreads();
        if (kc + 2 < NC) issue(kc + 2);
        CP_COMMIT();
    }

    // ---- epilogue: exp in registers -> fp16 p' + rowsum partials ----
#pragma unroll
    for (int mi = 0; mi < 4; mi++)
#pragma unroll
        for (int ni = 0; ni < 4; ni++)
#pragma unroll
            for (int q = 0; q < 4; q++)
                acc[mi][ni][q] = __expf(acc[mi][ni][q]);

    const int g = lane >> 2, cq = lane & 3;
    __half* pb = Ph + sP * b;
#pragma unroll
    for (int mi = 0; mi < 4; mi++) {
        const int r0 = m0 + wm * 64 + mi * 16 + g;
        const int r1 = r0 + 8;
#pragma unroll
        for (int ni = 0; ni < 4; ni++) {
            const int col = n0 + wn * 32 + ni * 8 + cq * 2;
            if (r0 < Mv)
                *(__half2*)(pb + (size_t)r0 * SDIM + col) =
                    __floats2half2_rn(acc[mi][ni][0], acc[mi][ni][1]);
            if (r1 < Mv)
                *(__half2*)(pb + (size_t)r1 * SDIM + col) =
                    __floats2half2_rn(acc[mi][ni][2], acc[mi][ni][3]);
        }
    }

    float ex[4][2];
#pragma unroll
    for (int mi = 0; mi < 4; mi++) {
        float s0 = 0.f, s1 = 0.f;
#pragma unroll
        for (int ni = 0; ni < 4; ni++) {
            s0 += acc[mi][ni][0] + acc[mi][ni][1];
            s1 += acc[mi][ni][2] + acc[mi][ni][3];
        }
        s0 += __shfl_xor_sync(0xffffffffu, s0, 1);
        s0 += __shfl_xor_sync(0xffffffffu, s0, 2);
        s1 += __shfl_xor_sync(0xffffffffu, s1, 1);
        s1 += __shfl_xor_sync(0xffffffffu, s1, 2);
        ex[mi][0] = s0; ex[mi][1] = s1;
    }
    __syncthreads();
    float* part = (float*)sm;               // [128][4]
    if (cq == 0) {
#pragma unroll
        for (int mi = 0; mi < 4; mi++) {
            part[(wm * 64 + mi * 16 + g) * 4 + wn] = ex[mi][0];
            part[(wm * 64 + mi * 16 + g + 8) * 4 + wn] = ex[mi][1];
        }
    }
    __syncthreads();
    if (tid < 128) {
        const int r = m0 + tid;
        if (r < Mv) {
            const float t = part[tid * 4] + part[tid * 4 + 1] +
                            part[tid * 4 + 2] + part[tid * 4 + 3];
            lpart[((size_t)b * CDIM + r) * NSLAB + blockIdx.x] = t;
        }
    }
}

// ---------------- inv: deterministic 32-slab reduce -> 1/l ------------------
__global__ void __launch_bounds__(256) inv_kernel(
    const float* __restrict__ lpart, float* __restrict__ linv)
{
    const int i = blockIdx.x * 256 + threadIdx.x;
    if (i < BDIM * CDIM) {
        const float* p = lpart + (size_t)i * NSLAB;
        float s = 0.f;
#pragma unroll
        for (int j = 0; j < NSLAB; j++) s += p[j];
        linv[i] = 1.0f / s;
    }
}

// ================= Fused GEMM2 + attn write (256 thr, D split) ==============
// Block = 128 c-rows x 128 D cols; grid.x = 2 n-tiles. 3-stage cp.async ring,
// wait_group 2 (only oldest). Staged p' (fp16) is the A operand; n-tile 0
// also writes attn = p'*1/l from its own staged bytes.
#define FKC 32
#define F2_T (128 * G1_PITCH)               // 10240 per operand per stage
#define F_A   512
#define F_B   (F_A + 3 * F2_T)              // 31232
#define F_TOTAL (F_B + 3 * F2_T)            // 61952

__global__ void __launch_bounds__(256, 2) fused_gemm2(
    const __half* __restrict__ Ph,          // p' [B,C,S] fp16
    const __half* __restrict__ xTh,
    const float* __restrict__ linv,
    float* __restrict__ attn,               // [B,C,S] fp32 out
    float* __restrict__ logits)             // [B,C,D] fp32 out
{
    extern __shared__ char sm[];
    const uint32_t sbase = smem_u32(sm);
    float* sl = (float*)sm;                 // 128 x 1/l

    const int tid = threadIdx.x;
    const int lane = tid & 31;
    const int wid = tid >> 5;
    const int wm = wid & 1;                 // 64-row slab
    const int wn = wid >> 1;                // 32-col slab (of 128)
    const int b = blockIdx.z;
    const int c0 = blockIdx.y * 128;
    const int n0 = blockIdx.x * 128;        // D offset
    const bool do_attn = (blockIdx.x == 0);
    const int Mv = CDIM;

    const __half* pb = Ph + (size_t)b * CDIM * SDIM;
    const __half* Bh = xTh + (size_t)b * DDIM * SDIM + (size_t)n0 * SDIM;
    float* ab = attn + (size_t)b * CDIM * SDIM;

    float acc[4][4][4];
#pragma unroll
    for (int i = 0; i < 4; i++)
#pragma unroll
        for (int j = 0; j < 4; j++)
#pragma unroll
            for (int q = 0; q < 4; q++) acc[i][j][q] = 0.f;

    if (tid < 128) {
        const int r = c0 + tid;
        sl[tid] = (r < Mv) ? linv[(size_t)b * CDIM + r] : 0.f;
    }

    auto issue = [&](int kc) {
        const int k0 = kc * FKC;
        const int s3 = kc % 3;
        const uint32_t stA = sbase + F_A + (uint32_t)s3 * F2_T;
        const uint32_t stB = sbase + F_B + (uint32_t)s3 * F2_T;
#pragma unroll
        for (int it = 0; it < 2; it++) {
            const int idx = tid + it * 256;
            const int row = idx >> 2, ch = idx & 3;
            const uint32_t soff = (uint32_t)(row * G1_PITCH + ch * 16);
            const int ra = c0 + row;
            const int sz = (ra < Mv) ? 16 : 0;
            const int rac = (ra < Mv) ? ra : (Mv - 1);
            cp16(stA + soff, pb + (size_t)rac * SDIM + k0 + ch * 8, sz);
            cp16(stB + soff, Bh + (size_t)row * SDIM + k0 + ch * 8, 16);
        }
    };

    issue(0); CP_COMMIT();
    issue(1); CP_COMMIT();
    issue(2); CP_COMMIT();
    __syncthreads();            // sl visible

    const uint32_t aoff = (uint32_t)((lane & 15) * G1_PITCH + (lane >> 4) * 16);
    const uint32_t boff = (uint32_t)(((lane & 7) + (lane >> 4) * 8) * G1_PITCH +
                                     ((lane >> 3) & 1) * 16);

    const int NC = SDIM / FKC;              // 128
    for (int kc = 0; kc < NC; kc++) {
        const int k0 = kc * FKC;
        const int s3 = kc % 3;
        CP_WAIT2();             // oldest group (kc) complete
        __syncthreads();

        // ---- attn write (n-tile 0 only; reads own staged bytes) ----
        if (do_attn) {
#pragma unroll
            for (int it = 0; it < 2; it++) {
                const int idx = tid + it * 256;
                const int row = idx >> 2, ch = idx & 3;
                const int ra = c0 + row;
                if (ra < Mv) {
                    const float iv = sl[row];
                    uint4 raw = *(const uint4*)(sm + F_A + s3 * F2_T +
                                                row * G1_PITCH + ch * 16);
                    const __half2* h2 = (const __half2*)&raw;
                    float2 a0 = __half22float2(h2[0]), a1 = __half22float2(h2[1]);
                    float2 a2 = __half22float2(h2[2]), a3 = __half22float2(h2[3]);
                    float* op = ab + (size_t)ra * SDIM + k0 + ch * 8;
                    *(float4*)op =
                        make_float4(a0.x * iv, a0.y * iv, a1.x * iv, a1.y * iv);
                    *(float4*)(op + 4) =
                        make_float4(a2.x * iv, a2.y * iv, a3.x * iv, a3.y * iv);
                }
            }
        }

        // ---- MMA: A = staged p', B = staged xT ----
        const uint32_t stA = sbase + F_A + (uint32_t)s3 * F2_T;
        const uint32_t stB = sbase + F_B + (uint32_t)s3 * F2_T;
#pragma unroll
        for (int ks = 0; ks < 2; ks++) {
            const uint32_t kb = ks * 32;
            uint32_t af[4][4], bf[2][4];
#pragma unroll
            for (int mi = 0; mi < 4; mi++)
                ldm4(af[mi], stA + (uint32_t)((wm * 64 + mi * 16) * G1_PITCH) + kb + aoff);
#pragma unroll
            for (int pi = 0; pi < 2; pi++)
                ldm4(bf[pi], stB + (uint32_t)((wn * 32 + pi * 16) * G1_PITCH) + kb + boff);
#pragma unroll
            for (int mi = 0; mi < 4; mi++)
#pragma unroll
                for (int ni = 0; ni < 4; ni++) {
                    const int p = ni >> 1, w2 = (ni & 1) * 2;
                    mma_h(acc[mi][ni], af[mi], bf[p][w2], bf[p][w2 + 1]);
                }
        }
        __syncthreads();        // stage kc reads done before reuse
        if (kc + 3 < NC) issue(kc + 3);
        CP_COMMIT();
    }

    // ---- epilogue: normalized logits ----
    float* ob = logits + (size_t)b * CDIM * DDIM;
    const int g = lane >> 2, cq = lane & 3;
#pragma unroll
    for (int mi = 0; mi < 4; mi++) {
        const int lr0 = wm * 64 + mi * 16 + g;
        const int lr1 = lr0 + 8;
        const float i0 = sl[lr0], i1 = sl[lr1];
        const int r0 = c0 + lr0, r1 = c0 + lr1;
#pragma unroll
        for (int ni = 0; ni < 4; ni++) {
            const int col = n0 + wn * 32 + ni * 8 + cq * 2;
            if (r0 < Mv)
                *(float2*)(ob + (size_t)r0 * DDIM + col) =
                    make_float2(acc[mi][ni][0] * i0, acc[mi][ni][1] * i0);
            if (r1 < Mv)
                *(float2*)(ob + (size_t)r1 * DDIM + col) =
                    make_float2(acc[mi][ni][2] * i1, acc[mi][ni][3] * i1);
        }
    }
}

// ---------------------------------------------------------------------------
extern "C" void kernel_launch(void* const* d_in, const int* in_sizes, int n_in,
                              void* d_out, int out_size)
{
    const float* x = (const float*)d_in[0];  // [B, S, D]
    const float* W = (const float*)d_in[1];  // [C, D]

    float* logits = (float*)d_out;                               // [B, C, D]
    float* attn   = (float*)d_out + (size_t)BDIM * CDIM * DDIM;  // [B, C, S]

    cudaFuncSetAttribute(gemm1_f16,
                         cudaFuncAttributeMaxDynamicSharedMemorySize, G1_TOTAL);
    cudaFuncSetAttribute(fused_gemm2,
                         cudaFuncAttributeMaxDynamicSharedMemorySize, F_TOTAL);

    void *p_xh, *p_xTh, *p_Wh, *p_ph, *p_lpart, *p_linv;
    cudaGetSymbolAddress(&p_xh, g_xh);
    cudaGetSymbolAddress(&p_xTh, g_xTh);
    cudaGetSymbolAddress(&p_Wh, g_Wh);
    cudaGetSymbolAddress(&p_ph, g_ph);
    cudaGetSymbolAddress(&p_lpart, g_lpart);
    cudaGetSymbolAddress(&p_linv, g_linv);

    // 1) fp16 conversions of W and x (+ transposed x)
    convert_W_kernel<<<(CDIM * DDIM + 255) / 256, 256>>>(W);
    convert_x_kernel<<<dim3(SDIM / 32, DDIM / 32, BDIM), dim3(32, 8)>>>(x);

    // 2) p' = exp(scores) fp16 + rowsum partials
    gemm1_f16<<<dim3(SDIM / 128, (CDIM + 127) / 128, BDIM), 256, G1_TOTAL>>>(
        (const __half*)p_Wh, (const __half*)p_xh, (size_t)SDIM * DDIM,
        (__half*)p_ph, (size_t)CDIM * SDIM, (float*)p_lpart, DDIM);

    // 3) 1/l per row
    inv_kernel<<<(BDIM * CDIM + 255) / 256, 256>>>(
        (const float*)p_lpart, (float*)p_linv);

    // 4) fused: logits = (p' @ xT^T)*1/l and attn = p'*1/l (n-tile 0)
    fused_gemm2<<<dim3(2, (CDIM + 127) / 128, BDIM), 256, F_TOTAL>>>(
        (const __half*)p_ph, (const __half*)p_xTh, (const float*)p_linv,
        attn, logits);
}

// round 14
// speedup vs baseline: 1.2299x; 1.0852x over previous
#include <cuda_runtime.h>
#include <cuda_fp16.h>
#include <cstdint>

// LabelwiseAttention: B=4, S=4096, D=256, C=8921
// scores = x @ W^T -> softmax over S -> logits = attn @ x
// Output: [logits (B*C*D) | attention (B*C*S)] fp32.
// GEMM1 (fp16 mma, 3-stage ring, 2 CTAs/SM) -> p' = exp(score) fp16 + rowsum
// partials. inv_kernel -> 1/l. Fused GEMM2 (256 thr, D split x2, 2 CTAs/SM):
// staged p' is the MMA A operand; attn = p'*1/l written from staged bytes,
// s-range split between the two n-tiles; logits scaled by 1/l in epilogue.

#define BDIM 4
#define SDIM 4096
#define DDIM 256
#define CDIM 8921
#define NSLAB (SDIM / 128)                 // 32 score slabs per row

// ---------------- scratch ---------------------------------------------------
__device__ __half g_xh[(size_t)BDIM * SDIM * DDIM];    // x  [b,s,d] fp16
__device__ __half g_xTh[(size_t)BDIM * DDIM * SDIM];   // xT [b,d,s] fp16
__device__ __half g_Wh[(size_t)CDIM * DDIM];           // W  [c,d]   fp16
__device__ __half g_ph[(size_t)BDIM * CDIM * SDIM];    // p' [b,c,s] fp16
__device__ float  g_lpart[(size_t)BDIM * CDIM * NSLAB];
__device__ float  g_linv[(size_t)BDIM * CDIM];

// ---------------- helpers ---------------------------------------------------
__device__ __forceinline__ uint32_t smem_u32(const void* p) {
    uint32_t a;
    asm("{ .reg .u64 t; cvta.to.shared.u64 t, %1; cvt.u32.u64 %0, t; }"
        : "=r"(a) : "l"(p));
    return a;
}

__device__ __forceinline__ void cp16(uint32_t dst, const void* src, int sz) {
    asm volatile("cp.async.cg.shared.global [%0], [%1], 16, %2;"
                 :: "r"(dst), "l"(src), "r"(sz) : "memory");
}
#define CP_COMMIT() asm volatile("cp.async.commit_group;" ::: "memory")
#define CP_WAIT2()  asm volatile("cp.async.wait_group 2;" ::: "memory")

__device__ __forceinline__ void ldm4(uint32_t* r, uint32_t addr) {
    asm volatile("ldmatrix.sync.aligned.m8n8.x4.shared.b16 {%0,%1,%2,%3}, [%4];"
                 : "=r"(r[0]), "=r"(r[1]), "=r"(r[2]), "=r"(r[3]) : "r"(addr));
}

__device__ __forceinline__ void mma_h(float* d, const uint32_t* a,
                                      uint32_t b0, uint32_t b1) {
    asm volatile(
        "mma.sync.aligned.m16n8k16.row.col.f32.f16.f16.f32 "
        "{%0,%1,%2,%3}, {%4,%5,%6,%7}, {%8,%9}, {%0,%1,%2,%3};"
        : "+f"(d[0]), "+f"(d[1]), "+f"(d[2]), "+f"(d[3])
        : "r"(a[0]), "r"(a[1]), "r"(a[2]), "r"(a[3]), "r"(b0), "r"(b1));
}

// ---------------- fp16 convert kernels --------------------------------------
__global__ void convert_W_kernel(const float* __restrict__ W) {
    int i = blockIdx.x * 256 + threadIdx.x;
    if (i < CDIM * DDIM) g_Wh[i] = __float2half(W[i]);
}

__global__ void convert_x_kernel(const float* __restrict__ x) {
    __shared__ __half t[32][33];
    const int b = blockIdx.z;
    const int s0 = blockIdx.x * 32, d0 = blockIdx.y * 32;
    const int tx = threadIdx.x, ty = threadIdx.y;  // 32x8
    const float* xb = x + (size_t)b * SDIM * DDIM;
#pragma unroll
    for (int i = 0; i < 32; i += 8) {
        const int s = s0 + ty + i;
        const __half h = __float2half(xb[(size_t)s * DDIM + d0 + tx]);
        g_xh[(size_t)b * SDIM * DDIM + (size_t)s * DDIM + d0 + tx] = h;
        t[ty + i][tx] = h;
    }
    __syncthreads();
#pragma unroll
    for (int i = 0; i < 32; i += 8) {
        const int d = d0 + ty + i;
        g_xTh[(size_t)b * DDIM * SDIM + (size_t)d * SDIM + s0 + tx] = t[tx][ty + i];
    }
}

// ---------------- GEMM1: p' = exp(Wh @ xh^T) fp16 + rowsum partials ---------
// 3-stage cp.async ring (prefetch distance 2), 2 CTAs/SM.
#define G1_PITCH 80
#define G1_TILE (128 * G1_PITCH)          // 10240 per operand
#define G1_ST (2 * G1_TILE)               // A + B per stage = 20480
#define G1_TOTAL (3 * G1_ST)              // 61440

__global__ void __launch_bounds__(256, 2) gemm1_f16(
    const __half* __restrict__ A,        // [CDIM, K] W fp16
    const __half* __restrict__ B,        // [SDIM, K] x fp16, batch strided
    size_t sB,
    __half* __restrict__ Ph, size_t sP,  // p' out, fp16
    float* __restrict__ lpart, int K)
{
    extern __shared__ char sm[];
    const uint32_t sbase = smem_u32(sm);

    const int tid = threadIdx.x;
    const int lane = tid & 31;
    const int wid = tid >> 5;
    const int wm = wid & 1;
    const int wn = wid >> 1;
    const int b = blockIdx.z;
    const int m0 = blockIdx.y * 128;
    const int n0 = blockIdx.x * 128;
    const int Mv = CDIM;

    const __half* Bb = B + sB * b;

    float acc[4][4][4];
#pragma unroll
    for (int i = 0; i < 4; i++)
#pragma unroll
        for (int j = 0; j < 4; j++)
#pragma unroll
            for (int q = 0; q < 4; q++) acc[i][j][q] = 0.f;

    const int NC = K / 32;               // 8

    auto issue = [&](int kc) {
        const uint32_t st = sbase + (uint32_t)(kc % 3) * G1_ST;
        const int k0 = kc * 32;
#pragma unroll
        for (int it = 0; it < 2; it++) {
            const int idx = tid + it * 256;
            const int row = idx >> 2, ch = idx & 3;
            const uint32_t soff = (uint32_t)(row * G1_PITCH + ch * 16);
            const int ra = m0 + row;
            const int sz = (ra < Mv) ? 16 : 0;
            const int rac = (ra < Mv) ? ra : (Mv - 1);
            cp16(st + soff, A + (size_t)rac * K + k0 + ch * 8, sz);
            cp16(st + G1_TILE + soff, Bb + (size_t)(n0 + row) * K + k0 + ch * 8, 16);
        }
    };

    issue(0); CP_COMMIT();
    issue(1); CP_COMMIT();
    issue(2); CP_COMMIT();

    const uint32_t aoff = (uint32_t)((lane & 15) * G1_PITCH + (lane >> 4) * 16);
    const uint32_t boff = (uint32_t)(((lane & 7) + (lane >> 4) * 8) * G1_PITCH +
                                     ((lane >> 3) & 1) * 16);

    for (int kc = 0; kc < NC; kc++) {
        CP_WAIT2();                      // oldest group (kc) complete
        __syncthreads();
        const uint32_t st = sbase + (uint32_t)(kc % 3) * G1_ST;

#pragma unroll
        for (int ks = 0; ks < 2; ks++) {
            const uint32_t kb = ks * 32;
            uint32_t af[4][4], bf[2][4];
#pragma unroll
            for (int mi = 0; mi < 4; mi++)
                ldm4(af[mi], st + (uint32_t)((wm * 64 + mi * 16) * G1_PITCH) + kb + aoff);
#pragma unroll
            for (int pi = 0; pi < 2; pi++)
                ldm4(bf[pi], st + G1_TILE +
                     (uint32_t)((wn * 32 + pi * 16) * G1_PITCH) + kb + boff);
#pragma unroll
            for (int mi = 0; mi < 4; mi++)
#pragma unroll
                for (int ni = 0; ni < 4; ni++) {
                    const int p = ni >> 1, w2 = (ni & 1) * 2;
                    mma_h(acc[mi][ni], af[mi], bf[p][w2], bf[p][w2 + 1]);
                }
        }
        __syncthreads();
        if (kc + 3 < NC) issue(kc + 3);
        CP_COMMIT();
    }

    // ---- epilogue: exp in registers -> fp16 p' + rowsum partials ----
#pragma unroll
    for (int mi = 0; mi < 4; mi++)
#pragma unroll
        for (int ni = 0; ni < 4; ni++)
#pragma unroll
            for (int q = 0; q < 4; q++)
                acc[mi][ni][q] = __expf(acc[mi][ni][q]);

    const int g = lane >> 2, cq = lane & 3;
    __half* pb = Ph + sP * b;
#pragma unroll
    for (int mi = 0; mi < 4; mi++) {
        const int r0 = m0 + wm * 64 + mi * 16 + g;
        const int r1 = r0 + 8;
#pragma unroll
        for (int ni = 0; ni < 4; ni++) {
            const int col = n0 + wn * 32 + ni * 8 + cq * 2;
            if (r0 < Mv)
                *(__half2*)(pb + (size_t)r0 * SDIM + col) =
                    __floats2half2_rn(acc[mi][ni][0], acc[mi][ni][1]);
            if (r1 < Mv)
                *(__half2*)(pb + (size_t)r1 * SDIM + col) =
                    __floats2half2_rn(acc[mi][ni][2], acc[mi][ni][3]);
        }
    }

    float ex[4][2];
#pragma unroll
    for (int mi = 0; mi < 4; mi++) {
        float s0 = 0.f, s1 = 0.f;
#pragma unroll
        for (int ni = 0; ni < 4; ni++) {
            s0 += acc[mi][ni][0] + acc[mi][ni][1];
            s1 += acc[mi][ni][2] + acc[mi][ni][3];
        }
        s0 += __shfl_xor_sync(0xffffffffu, s0, 1);
        s0 += __shfl_xor_sync(0xffffffffu, s0, 2);
        s1 += __shfl_xor_sync(0xffffffffu, s1, 1);
        s1 += __shfl_xor_sync(0xffffffffu, s1, 2);
        ex[mi][0] = s0; ex[mi][1] = s1;
    }
    __syncthreads();
    float* part = (float*)sm;               // [128][4]
    if (cq == 0) {
#pragma unroll
        for (int mi = 0; mi < 4; mi++) {
            part[(wm * 64 + mi * 16 + g) * 4 + wn] = ex[mi][0];
            part[(wm * 64 + mi * 16 + g + 8) * 4 + wn] = ex[mi][1];
        }
    }
    __syncthreads();
    if (tid < 128) {
        const int r = m0 + tid;
        if (r < Mv) {
            const float t = part[tid * 4] + part[tid * 4 + 1] +
                            part[tid * 4 + 2] + part[tid * 4 + 3];
            lpart[((size_t)b * CDIM + r) * NSLAB + blockIdx.x] = t;
        }
    }
}

// ---------------- inv: deterministic 32-slab reduce -> 1/l ------------------
__global__ void __launch_bounds__(256) inv_kernel(
    const float* __restrict__ lpart, float* __restrict__ linv)
{
    const int i = blockIdx.x * 256 + threadIdx.x;
    if (i < BDIM * CDIM) {
        const float* p = lpart + (size_t)i * NSLAB;
        float s = 0.f;
#pragma unroll
        for (int j = 0; j < NSLAB; j++) s += p[j];
        linv[i] = 1.0f / s;
    }
}

// ================= Fused GEMM2 + attn write (256 thr, D split) ==============
// Block = 128 c-rows x 128 D cols; grid.x = 2 n-tiles. 3-stage cp.async ring.
// attn write split by K-range: n-tile 0 handles kc < NC/2, n-tile 1 the rest.
#define FKC 32
#define F2_T (128 * G1_PITCH)               // 10240 per operand per stage
#define F_A   512
#define F_B   (F_A + 3 * F2_T)              // 31232
#define F_TOTAL (F_B + 3 * F2_T)            // 61952

__global__ void __launch_bounds__(256, 2) fused_gemm2(
    const __half* __restrict__ Ph,          // p' [B,C,S] fp16
    const __half* __restrict__ xTh,
    const float* __restrict__ linv,
    float* __restrict__ attn,               // [B,C,S] fp32 out
    float* __restrict__ logits)             // [B,C,D] fp32 out
{
    extern __shared__ char sm[];
    const uint32_t sbase = smem_u32(sm);
    float* sl = (float*)sm;                 // 128 x 1/l

    const int tid = threadIdx.x;
    const int lane = tid & 31;
    const int wid = tid >> 5;
    const int wm = wid & 1;                 // 64-row slab
    const int wn = wid >> 1;                // 32-col slab (of 128)
    const int b = blockIdx.z;
    const int c0 = blockIdx.y * 128;
    const int n0 = blockIdx.x * 128;        // D offset
    const int Mv = CDIM;

    const __half* pb = Ph + (size_t)b * CDIM * SDIM;
    const __half* Bh = xTh + (size_t)b * DDIM * SDIM + (size_t)n0 * SDIM;
    float* ab = attn + (size_t)b * CDIM * SDIM;

    float acc[4][4][4];
#pragma unroll
    for (int i = 0; i < 4; i++)
#pragma unroll
        for (int j = 0; j < 4; j++)
#pragma unroll
            for (int q = 0; q < 4; q++) acc[i][j][q] = 0.f;

    if (tid < 128) {
        const int r = c0 + tid;
        sl[tid] = (r < Mv) ? linv[(size_t)b * CDIM + r] : 0.f;
    }

    auto issue = [&](int kc) {
        const int k0 = kc * FKC;
        const int s3 = kc % 3;
        const uint32_t stA = sbase + F_A + (uint32_t)s3 * F2_T;
        const uint32_t stB = sbase + F_B + (uint32_t)s3 * F2_T;
#pragma unroll
        for (int it = 0; it < 2; it++) {
            const int idx = tid + it * 256;
            const int row = idx >> 2, ch = idx & 3;
            const uint32_t soff = (uint32_t)(row * G1_PITCH + ch * 16);
            const int ra = c0 + row;
            const int sz = (ra < Mv) ? 16 : 0;
            const int rac = (ra < Mv) ? ra : (Mv - 1);
            cp16(stA + soff, pb + (size_t)rac * SDIM + k0 + ch * 8, sz);
            cp16(stB + soff, Bh + (size_t)row * SDIM + k0 + ch * 8, 16);
        }
    };

    issue(0); CP_COMMIT();
    issue(1); CP_COMMIT();
    issue(2); CP_COMMIT();
    __syncthreads();            // sl visible

    const uint32_t aoff = (uint32_t)((lane & 15) * G1_PITCH + (lane >> 4) * 16);
    const uint32_t boff = (uint32_t)(((lane & 7) + (lane >> 4) * 8) * G1_PITCH +
                                     ((lane >> 3) & 1) * 16);

    const int NC = SDIM / FKC;              // 128
    for (int kc = 0; kc < NC; kc++) {
        const int k0 = kc * FKC;
        const int s3 = kc % 3;
        CP_WAIT2();             // oldest group (kc) complete
        __syncthreads();

        // ---- attn write: split s-range between the two n-tiles ----
        const bool do_write = (blockIdx.x == 0) ? (kc < NC / 2) : (kc >= NC / 2);
        if (do_write) {
#pragma unroll
            for (int it = 0; it < 2; it++) {
                const int idx = tid + it * 256;
                const int row = idx >> 2, ch = idx & 3;
                const int ra = c0 + row;
                if (ra < Mv) {
                    const float iv = sl[row];
                    uint4 raw = *(const uint4*)(sm + F_A + s3 * F2_T +
                                                row * G1_PITCH + ch * 16);
                    const __half2* h2 = (const __half2*)&raw;
                    float2 a0 = __half22float2(h2[0]), a1 = __half22float2(h2[1]);
                    float2 a2 = __half22float2(h2[2]), a3 = __half22float2(h2[3]);
                    float* op = ab + (size_t)ra * SDIM + k0 + ch * 8;
                    *(float4*)op =
                        make_float4(a0.x * iv, a0.y * iv, a1.x * iv, a1.y * iv);
                    *(float4*)(op + 4) =
                        make_float4(a2.x * iv, a2.y * iv, a3.x * iv, a3.y * iv);
                }
            }
        }

        // ---- MMA: A = staged p', B = staged xT ----
        const uint32_t stA = sbase + F_A + (uint32_t)s3 * F2_T;
        const uint32_t stB = sbase + F_B + (uint32_t)s3 * F2_T;
#pragma unroll
        for (int ks = 0; ks < 2; ks++) {
            const uint32_t kb = ks * 32;
            uint32_t af[4][4], bf[2][4];
#pragma unroll
            for (int mi = 0; mi < 4; mi++)
                ldm4(af[mi], stA + (uint32_t)((wm * 64 + mi * 16) * G1_PITCH) + kb + aoff);
#pragma unroll
            for (int pi = 0; pi < 2; pi++)
                ldm4(bf[pi], stB + (uint32_t)((wn * 32 + pi * 16) * G1_PITCH) + kb + boff);
#pragma unroll
            for (int mi = 0; mi < 4; mi++)
#pragma unroll
                for (int ni = 0; ni < 4; ni++) {
                    const int p = ni >> 1, w2 = (ni & 1) * 2;
                    mma_h(acc[mi][ni], af[mi], bf[p][w2], bf[p][w2 + 1]);
                }
        }
        __syncthreads();        // stage kc reads done before reuse
        if (kc + 3 < NC) issue(kc + 3);
        CP_COMMIT();
    }

    // ---- epilogue: normalized logits ----
    float* ob = logits + (size_t)b * CDIM * DDIM;
    const int g = lane >> 2, cq = lane & 3;
#pragma unroll
    for (int mi = 0; mi < 4; mi++) {
        const int lr0 = wm * 64 + mi * 16 + g;
        const int lr1 = lr0 + 8;
        const float i0 = sl[lr0], i1 = sl[lr1];
        const int r0 = c0 + lr0, r1 = c0 + lr1;
#pragma unroll
        for (int ni = 0; ni < 4; ni++) {
            const int col = n0 + wn * 32 + ni * 8 + cq * 2;
            if (r0 < Mv)
                *(float2*)(ob + (size_t)r0 * DDIM + col) =
                    make_float2(acc[mi][ni][0] * i0, acc[mi][ni][1] * i0);
            if (r1 < Mv)
                *(float2*)(ob + (size_t)r1 * DDIM + col) =
                    make_float2(acc[mi][ni][2] * i1, acc[mi][ni][3] * i1);
        }
    }
}

// ---------------------------------------------------------------------------
extern "C" void kernel_launch(void* const* d_in, const int* in_sizes, int n_in,
                              void* d_out, int out_size)
{
    const float* x = (const float*)d_in[0];  // [B, S, D]
    const float* W = (const float*)d_in[1];  // [C, D]

    float* logits = (float*)d_out;                               // [B, C, D]
    float* attn   = (float*)d_out + (size_t)BDIM * CDIM * DDIM;  // [B, C, S]

    cudaFuncSetAttribute(gemm1_f16,
                         cudaFuncAttributeMaxDynamicSharedMemorySize, G1_TOTAL);
    cudaFuncSetAttribute(fused_gemm2,
                         cudaFuncAttributeMaxDynamicSharedMemorySize, F_TOTAL);

    void *p_xh, *p_xTh, *p_Wh, *p_ph, *p_lpart, *p_linv;
    cudaGetSymbolAddress(&p_xh, g_xh);
    cudaGetSymbolAddress(&p_xTh, g_xTh);
    cudaGetSymbolAddress(&p_Wh, g_Wh);
    cudaGetSymbolAddress(&p_ph, g_ph);
    cudaGetSymbolAddress(&p_lpart, g_lpart);
    cudaGetSymbolAddress(&p_linv, g_linv);

    // 1) fp16 conversions of W and x (+ transposed x)
    convert_W_kernel<<<(CDIM * DDIM + 255) / 256, 256>>>(W);
    convert_x_kernel<<<dim3(SDIM / 32, DDIM / 32, BDIM), dim3(32, 8)>>>(x);

    // 2) p' = exp(scores) fp16 + rowsum partials
    gemm1_f16<<<dim3(SDIM / 128, (CDIM + 127) / 128, BDIM), 256, G1_TOTAL>>>(
        (const __half*)p_Wh, (const __half*)p_xh, (size_t)SDIM * DDIM,
        (__half*)p_ph, (size_t)CDIM * SDIM, (float*)p_lpart, DDIM);

    // 3) 1/l per row
    inv_kernel<<<(BDIM * CDIM + 255) / 256, 256>>>(
        (const float*)p_lpart, (float*)p_linv);

    // 4) fused: logits = (p' @ xT^T)*1/l and attn = p'*1/l (s-split)
    fused_gemm2<<<dim3(2, (CDIM + 127) / 128, BDIM), 256, F_TOTAL>>>(
        (const __half*)p_ph, (const __half*)p_xTh, (const float*)p_linv,
        attn, logits);
}

// round 16
// speedup vs baseline: 1.3240x; 1.0765x over previous
#include <cuda_runtime.h>
#include <cuda_fp16.h>
#include <cstdint>

// LabelwiseAttention: B=4, S=4096, D=256, C=8921
// scores = x @ W^T -> softmax over S -> logits = attn @ x
// Output: [logits (B*C*D) | attention (B*C*S)] fp32.
// GEMM1 (fp16 mma, FKC=64, 3-stage ring, 2 CTAs/SM) -> p' = exp(score) fp16
// + rowsum partials. inv_kernel -> 1/l. Fused GEMM2 (FKC=64, D split x2,
// 2 CTAs/SM): staged p' is the MMA A operand; attn = p'*1/l from staged
// bytes (s-range split across n-tiles); logits scaled in epilogue.
// R15 fix: sl table moved OUTSIDE the staging ring (was overlapping stage 2).

#define BDIM 4
#define SDIM 4096
#define DDIM 256
#define CDIM 8921
#define NSLAB (SDIM / 128)                 // 32 score slabs per row

#define PITCH 144                          // 128B row data + 16B pad
#define TILEB (128 * PITCH)                // 18432 per operand per stage
#define STAGEB (2 * TILEB)                 // 36864
#define SM_TOT (3 * STAGEB)                // 110592
#define F_TOTAL (SM_TOT + 512)             // ring + sl table (fused kernel)

// ---------------- scratch ---------------------------------------------------
__device__ __half g_xh[(size_t)BDIM * SDIM * DDIM];    // x  [b,s,d] fp16
__device__ __half g_xTh[(size_t)BDIM * DDIM * SDIM];   // xT [b,d,s] fp16
__device__ __half g_Wh[(size_t)CDIM * DDIM];           // W  [c,d]   fp16
__device__ __half g_ph[(size_t)BDIM * CDIM * SDIM];    // p' [b,c,s] fp16
__device__ float  g_lpart[(size_t)BDIM * CDIM * NSLAB];
__device__ float  g_linv[(size_t)BDIM * CDIM];

// ---------------- helpers ---------------------------------------------------
__device__ __forceinline__ uint32_t smem_u32(const void* p) {
    uint32_t a;
    asm("{ .reg .u64 t; cvta.to.shared.u64 t, %1; cvt.u32.u64 %0, t; }"
        : "=r"(a) : "l"(p));
    return a;
}

__device__ __forceinline__ void cp16(uint32_t dst, const void* src, int sz) {
    asm volatile("cp.async.cg.shared.global [%0], [%1], 16, %2;"
                 :: "r"(dst), "l"(src), "r"(sz) : "memory");
}
#define CP_COMMIT() asm volatile("cp.async.commit_group;" ::: "memory")
#define CP_WAIT2()  asm volatile("cp.async.wait_group 2;" ::: "memory")

__device__ __forceinline__ void ldm4(uint32_t* r, uint32_t addr) {
    asm volatile("ldmatrix.sync.aligned.m8n8.x4.shared.b16 {%0,%1,%2,%3}, [%4];"
                 : "=r"(r[0]), "=r"(r[1]), "=r"(r[2]), "=r"(r[3]) : "r"(addr));
}

__device__ __forceinline__ void mma_h(float* d, const uint32_t* a,
                                      uint32_t b0, uint32_t b1) {
    asm volatile(
        "mma.sync.aligned.m16n8k16.row.col.f32.f16.f16.f32 "
        "{%0,%1,%2,%3}, {%4,%5,%6,%7}, {%8,%9}, {%0,%1,%2,%3};"
        : "+f"(d[0]), "+f"(d[1]), "+f"(d[2]), "+f"(d[3])
        : "r"(a[0]), "r"(a[1]), "r"(a[2]), "r"(a[3]), "r"(b0), "r"(b1));
}

// ---------------- fp16 convert kernels --------------------------------------
__global__ void convert_W_kernel(const float* __restrict__ W) {
    int i = blockIdx.x * 256 + threadIdx.x;
    if (i < CDIM * DDIM) g_Wh[i] = __float2half(W[i]);
}

__global__ void convert_x_kernel(const float* __restrict__ x) {
    __shared__ __half t[32][33];
    const int b = blockIdx.z;
    const int s0 = blockIdx.x * 32, d0 = blockIdx.y * 32;
    const int tx = threadIdx.x, ty = threadIdx.y;  // 32x8
    const float* xb = x + (size_t)b * SDIM * DDIM;
#pragma unroll
    for (int i = 0; i < 32; i += 8) {
        const int s = s0 + ty + i;
        const __half h = __float2half(xb[(size_t)s * DDIM + d0 + tx]);
        g_xh[(size_t)b * SDIM * DDIM + (size_t)s * DDIM + d0 + tx] = h;
        t[ty + i][tx] = h;
    }
    __syncthreads();
#pragma unroll
    for (int i = 0; i < 32; i += 8) {
        const int d = d0 + ty + i;
        g_xTh[(size_t)b * DDIM * SDIM + (size_t)d * SDIM + s0 + tx] = t[tx][ty + i];
    }
}

// ---------------- GEMM1: p' = exp(Wh @ xh^T) fp16 + rowsum partials ---------
// FKC=64: K=256 -> 4 chunks; 3-stage ring.
__global__ void __launch_bounds__(256, 2) gemm1_f16(
    const __half* __restrict__ A,        // [CDIM, K] W fp16
    const __half* __restrict__ B,        // [SDIM, K] x fp16, batch strided
    size_t sB,
    __half* __restrict__ Ph, size_t sP,  // p' out, fp16
    float* __restrict__ lpart, int K)
{
    extern __shared__ char sm[];
    const uint32_t sbase = smem_u32(sm);

    const int tid = threadIdx.x;
    const int lane = tid & 31;
    const int wid = tid >> 5;
    const int wm = wid & 1;
    const int wn = wid >> 1;
    const int b = blockIdx.z;
    const int m0 = blockIdx.y * 128;
    const int n0 = blockIdx.x * 128;
    const int Mv = CDIM;

    const __half* Bb = B + sB * b;

    float acc[4][4][4];
#pragma unroll
    for (int i = 0; i < 4; i++)
#pragma unroll
        for (int j = 0; j < 4; j++)
#pragma unroll
            for (int q = 0; q < 4; q++) acc[i][j][q] = 0.f;

    const int NC = K / 64;               // 4

    auto issue = [&](int kc) {
        const uint32_t st = sbase + (uint32_t)(kc % 3) * STAGEB;
        const int k0 = kc * 64;
#pragma unroll
        for (int it = 0; it < 4; it++) {
            const int idx = tid + it * 256;      // 1024: 128 rows x 8 chunks
            const int row = idx >> 3, ch = idx & 7;
            const uint32_t soff = (uint32_t)(row * PITCH + ch * 16);
            const int ra = m0 + row;
            const int sz = (ra < Mv) ? 16 : 0;
            const int rac = (ra < Mv) ? ra : (Mv - 1);
            cp16(st + soff, A + (size_t)rac * K + k0 + ch * 8, sz);
            cp16(st + TILEB + soff, Bb + (size_t)(n0 + row) * K + k0 + ch * 8, 16);
        }
    };

    issue(0); CP_COMMIT();
    issue(1); CP_COMMIT();
    issue(2); CP_COMMIT();

    const uint32_t aoff = (uint32_t)((lane & 15) * PITCH + (lane >> 4) * 16);
    const uint32_t boff = (uint32_t)(((lane & 7) + (lane >> 4) * 8) * PITCH +
                                     ((lane >> 3) & 1) * 16);

    for (int kc = 0; kc < NC; kc++) {
        CP_WAIT2();                      // group kc complete
        __syncthreads();
        const uint32_t st = sbase + (uint32_t)(kc % 3) * STAGEB;

#pragma unroll
        for (int ks = 0; ks < 4; ks++) {
            const uint32_t kb = ks * 32;
            uint32_t af[4][4], bf[2][4];
#pragma unroll
            for (int mi = 0; mi < 4; mi++)
                ldm4(af[mi], st + (uint32_t)((wm * 64 + mi * 16) * PITCH) + kb + aoff);
#pragma unroll
            for (int pi = 0; pi < 2; pi++)
                ldm4(bf[pi], st + TILEB +
                     (uint32_t)((wn * 32 + pi * 16) * PITCH) + kb + boff);
#pragma unroll
            for (int mi = 0; mi < 4; mi++)
#pragma unroll
                for (int ni = 0; ni < 4; ni++) {
                    const int p = ni >> 1, w2 = (ni & 1) * 2;
                    mma_h(acc[mi][ni], af[mi], bf[p][w2], bf[p][w2 + 1]);
                }
        }
        __syncthreads();
        if (kc + 3 < NC) issue(kc + 3);
        CP_COMMIT();
    }

    // ---- epilogue: exp in registers -> fp16 p' + rowsum partials ----
#pragma unroll
    for (int mi = 0; mi < 4; mi++)
#pragma unroll
        for (int ni = 0; ni < 4; ni++)
#pragma unroll
            for (int q = 0; q < 4; q++)
                acc[mi][ni][q] = __expf(acc[mi][ni][q]);

    const int g = lane >> 2, cq = lane & 3;
    __half* pb = Ph + sP * b;
#pragma unroll
    for (int mi = 0; mi < 4; mi++) {
        const int r0 = m0 + wm * 64 + mi * 16 + g;
        const int r1 = r0 + 8;
#pragma unroll
        for (int ni = 0; ni < 4; ni++) {
            const int col = n0 + wn * 32 + ni * 8 + cq * 2;
            if (r0 < Mv)
                *(__half2*)(pb + (size_t)r0 * SDIM + col) =
                    __floats2half2_rn(acc[mi][ni][0], acc[mi][ni][1]);
            if (r1 < Mv)
                *(__half2*)(pb + (size_t)r1 * SDIM + col) =
                    __floats2half2_rn(acc[mi][ni][2], acc[mi][ni][3]);
        }
    }

    float ex[4][2];
#pragma unroll
    for (int mi = 0; mi < 4; mi++) {
        float s0 = 0.f, s1 = 0.f;
#pragma unroll
        for (int ni = 0; ni < 4; ni++) {
            s0 += acc[mi][ni][0] + acc[mi][ni][1];
            s1 += acc[mi][ni][2] + acc[mi][ni][3];
        }
        s0 += __shfl_xor_sync(0xffffffffu, s0, 1);
        s0 += __shfl_xor_sync(0xffffffffu, s0, 2);
        s1 += __shfl_xor_sync(0xffffffffu, s1, 1);
        s1 += __shfl_xor_sync(0xffffffffu, s1, 2);
        ex[mi][0] = s0; ex[mi][1] = s1;
    }
    __syncthreads();                     // all cp.async groups drained by now
    float* part = (float*)sm;            // [128][4] (stage 0 reuse, safe)
    if (cq == 0) {
#pragma unroll
        for (int mi = 0; mi < 4; mi++) {
            part[(wm * 64 + mi * 16 + g) * 4 + wn] = ex[mi][0];
            part[(wm * 64 + mi * 16 + g + 8) * 4 + wn] = ex[mi][1];
        }
    }
    __syncthreads();
    if (tid < 128) {
        const int r = m0 + tid;
        if (r < Mv) {
            const float t = part[tid * 4] + part[tid * 4 + 1] +
                            part[tid * 4 + 2] + part[tid * 4 + 3];
            lpart[((size_t)b * CDIM + r) * NSLAB + blockIdx.x] = t;
        }
    }
}

// ---------------- inv: deterministic 32-slab reduce -> 1/l ------------------
__global__ void __launch_bounds__(256) inv_kernel(
    const float* __restrict__ lpart, float* __restrict__ linv)
{
    const int i = blockIdx.x * 256 + threadIdx.x;
    if (i < BDIM * CDIM) {
        const float* p = lpart + (size_t)i * NSLAB;
        float s = 0.f;
#pragma unroll
        for (int j = 0; j < NSLAB; j++) s += p[j];
        linv[i] = 1.0f / s;
    }
}

// ================= Fused GEMM2 + attn write (FKC=64, D split) ===============
// Block = 128 c-rows x 128 D cols; grid.x = 2 n-tiles. 3-stage ring, 64
// iterations; attn write split by s-range across n-tiles. sl at SM_TOT (past
// the ring).
__global__ void __launch_bounds__(256, 2) fused_gemm2(
    const __half* __restrict__ Ph,          // p' [B,C,S] fp16
    const __half* __restrict__ xTh,
    const float* __restrict__ linv,
    float* __restrict__ attn,               // [B,C,S] fp32 out
    float* __restrict__ logits)             // [B,C,D] fp32 out
{
    extern __shared__ char sm[];
    const uint32_t sbase = smem_u32(sm);
    float* sl = (float*)(sm + SM_TOT);      // 128 x 1/l, OUTSIDE the ring

    const int tid = threadIdx.x;
    const int lane = tid & 31;
    const int wid = tid >> 5;
    const int wm = wid & 1;                 // 64-row slab
    const int wn = wid >> 1;                // 32-col slab (of 128)
    const int b = blockIdx.z;
    const int c0 = blockIdx.y * 128;
    const int n0 = blockIdx.x * 128;        // D offset
    const int Mv = CDIM;

    const __half* pb = Ph + (size_t)b * CDIM * SDIM;
    const __half* Bh = xTh + (size_t)b * DDIM * SDIM + (size_t)n0 * SDIM;
    float* ab = attn + (size_t)b * CDIM * SDIM;

    float acc[4][4][4];
#pragma unroll
    for (int i = 0; i < 4; i++)
#pragma unroll
        for (int j = 0; j < 4; j++)
#pragma unroll
            for (int q = 0; q < 4; q++) acc[i][j][q] = 0.f;

    if (tid < 128) {
        const int r = c0 + tid;
        sl[tid] = (r < Mv) ? linv[(size_t)b * CDIM + r] : 0.f;
    }

    auto issue = [&](int kc) {
        const int k0 = kc * 64;
        const uint32_t st = sbase + (uint32_t)(kc % 3) * STAGEB;
#pragma unroll
        for (int it = 0; it < 4; it++) {
            const int idx = tid + it * 256;      // 1024: 128 rows x 8 chunks
            const int row = idx >> 3, ch = idx & 7;
            const uint32_t soff = (uint32_t)(row * PITCH + ch * 16);
            const int ra = c0 + row;
            const int sz = (ra < Mv) ? 16 : 0;
            const int rac = (ra < Mv) ? ra : (Mv - 1);
            cp16(st + soff, pb + (size_t)rac * SDIM + k0 + ch * 8, sz);
            cp16(st + TILEB + soff, Bh + (size_t)row * SDIM + k0 + ch * 8, 16);
        }
    };

    issue(0); CP_COMMIT();
    issue(1); CP_COMMIT();
    issue(2); CP_COMMIT();
    __syncthreads();            // sl visible

    const uint32_t aoff = (uint32_t)((lane & 15) * PITCH + (lane >> 4) * 16);
    const uint32_t boff = (uint32_t)(((lane & 7) + (lane >> 4) * 8) * PITCH +
                                     ((lane >> 3) & 1) * 16);

    const int NC = SDIM / 64;               // 64
    for (int kc = 0; kc < NC; kc++) {
        const int k0 = kc * 64;
        const uint32_t st = sbase + (uint32_t)(kc % 3) * STAGEB;
        CP_WAIT2();             // group kc complete
        __syncthreads();

        // ---- attn write: s-range split between the two n-tiles ----
        const bool do_write = (blockIdx.x == 0) ? (kc < NC / 2) : (kc >= NC / 2);
        if (do_write) {
#pragma unroll
            for (int it = 0; it < 4; it++) {
                const int idx = tid + it * 256;
                const int row = idx >> 3, ch = idx & 7;
                const int ra = c0 + row;
                if (ra < Mv) {
                    const float iv = sl[row];
                    uint4 raw = *(const uint4*)(sm + (kc % 3) * STAGEB +
                                                row * PITCH + ch * 16);
                    const __half2* h2 = (const __half2*)&raw;
                    float2 a0 = __half22float2(h2[0]), a1 = __half22float2(h2[1]);
                    float2 a2 = __half22float2(h2[2]), a3 = __half22float2(h2[3]);
                    float* op = ab + (size_t)ra * SDIM + k0 + ch * 8;
                    *(float4*)op =
                        make_float4(a0.x * iv, a0.y * iv, a1.x * iv, a1.y * iv);
                    *(float4*)(op + 4) =
                        make_float4(a2.x * iv, a2.y * iv, a3.x * iv, a3.y * iv);
                }
            }
        }

        // ---- MMA: A = staged p', B = staged xT ----
#pragma unroll
        for (int ks = 0; ks < 4; ks++) {
            const uint32_t kb = ks * 32;
            uint32_t af[4][4], bf[2][4];
#pragma unroll
            for (int mi = 0; mi < 4; mi++)
                ldm4(af[mi], st + (uint32_t)((wm * 64 + mi * 16) * PITCH) + kb + aoff);
#pragma unroll
            for (int pi = 0; pi < 2; pi++)
                ldm4(bf[pi], st + TILEB +
                     (uint32_t)((wn * 32 + pi * 16) * PITCH) + kb + boff);
#pragma unroll
            for (int mi = 0; mi < 4; mi++)
#pragma unroll
                for (int ni = 0; ni < 4; ni++) {
                    const int p = ni >> 1, w2 = (ni & 1) * 2;
                    mma_h(acc[mi][ni], af[mi], bf[p][w2], bf[p][w2 + 1]);
                }
        }
        __syncthreads();        // stage kc reads done before reuse
        if (kc + 3 < NC) issue(kc + 3);
        CP_COMMIT();
    }

    // ---- epilogue: normalized logits ----
    float* ob = logits + (size_t)b * CDIM * DDIM;
    const int g = lane >> 2, cq = lane & 3;
#pragma unroll
    for (int mi = 0; mi < 4; mi++) {
        const int lr0 = wm * 64 + mi * 16 + g;
        const int lr1 = lr0 + 8;
        const float i0 = sl[lr0], i1 = sl[lr1];
        const int r0 = c0 + lr0, r1 = c0 + lr1;
#pragma unroll
        for (int ni = 0; ni < 4; ni++) {
            const int col = n0 + wn * 32 + ni * 8 + cq * 2;
            if (r0 < Mv)
                *(float2*)(ob + (size_t)r0 * DDIM + col) =
                    make_float2(acc[mi][ni][0] * i0, acc[mi][ni][1] * i0);
            if (r1 < Mv)
                *(float2*)(ob + (size_t)r1 * DDIM + col) =
                    make_float2(acc[mi][ni][2] * i1, acc[mi][ni][3] * i1);
        }
    }
}

// ---------------------------------------------------------------------------
extern "C" void kernel_launch(void* const* d_in, const int* in_sizes, int n_in,
                              void* d_out, int out_size)
{
    const float* x = (const float*)d_in[0];  // [B, S, D]
    const float* W = (const float*)d_in[1];  // [C, D]

    float* logits = (float*)d_out;                               // [B, C, D]
    float* attn   = (float*)d_out + (size_t)BDIM * CDIM * DDIM;  // [B, C, S]

    cudaFuncSetAttribute(gemm1_f16,
                         cudaFuncAttributeMaxDynamicSharedMemorySize, SM_TOT);
    cudaFuncSetAttribute(fused_gemm2,
                         cudaFuncAttributeMaxDynamicSharedMemorySize, F_TOTAL);

    void *p_xh, *p_xTh, *p_Wh, *p_ph, *p_lpart, *p_linv;
    cudaGetSymbolAddress(&p_xh, g_xh);
    cudaGetSymbolAddress(&p_xTh, g_xTh);
    cudaGetSymbolAddress(&p_Wh, g_Wh);
    cudaGetSymbolAddress(&p_ph, g_ph);
    cudaGetSymbolAddress(&p_lpart, g_lpart);
    cudaGetSymbolAddress(&p_linv, g_linv);

    // 1) fp16 conversions of W and x (+ transposed x)
    convert_W_kernel<<<(CDIM * DDIM + 255) / 256, 256>>>(W);
    convert_x_kernel<<<dim3(SDIM / 32, DDIM / 32, BDIM), dim3(32, 8)>>>(x);

    // 2) p' = exp(scores) fp16 + rowsum partials
    gemm1_f16<<<dim3(SDIM / 128, (CDIM + 127) / 128, BDIM), 256, SM_TOT>>>(
        (const __half*)p_Wh, (const __half*)p_xh, (size_t)SDIM * DDIM,
        (__half*)p_ph, (size_t)CDIM * SDIM, (float*)p_lpart, DDIM);

    // 3) 1/l per row
    inv_kernel<<<(BDIM * CDIM + 255) / 256, 256>>>(
        (const float*)p_lpart, (float*)p_linv);

    // 4) fused: logits = (p' @ xT^T)*1/l and attn = p'*1/l (s-split)
    fused_gemm2<<<dim3(2, (CDIM + 127) / 128, BDIM), 256, F_TOTAL>>>(
        (const __half*)p_ph, (const __half*)p_xTh, (const float*)p_linv,
        attn, logits);
}